// round 6
// baseline (speedup 1.0000x reference)
#include <cuda_runtime.h>
#include <cstdint>

#define N_NODES 100000
#define N_EDGES 1600000
#define HID 128
#define NBLK ((N_NODES + 255) / 256)     // 391
#define N_TILES ((N_NODES + 127) / 128)  // 782

// ---------------- scratch ----------------------------------------------------
__device__ __align__(16) float g_buf0[(size_t)N_NODES * HID]; // xts = dinv.*(X@W)
__device__ __align__(16) float g_buf1[(size_t)N_NODES * HID]; // layer-1 hidden
__device__ float g_dinv[N_NODES];
__device__ int   g_deg[N_NODES];
__device__ int   g_cur[N_NODES];
__device__ int   g_off[N_NODES + 1];
__device__ int   g_src[N_EDGES];
__device__ int   g_bsum[NBLK + 1];
__device__ int   g_is64;

// ---------------- helpers ----------------------------------------------------
__device__ __forceinline__ uint32_t f2tf32(float f) {
    uint32_t r;
    asm("cvt.rna.tf32.f32 %0, %1;" : "=r"(r) : "f"(f));
    return r;
}

__device__ __forceinline__ void mma_tf32(float c[4], const uint32_t a[4],
                                         uint32_t b0, uint32_t b1) {
    asm("mma.sync.aligned.m16n8k8.row.col.f32.tf32.tf32.f32 "
        "{%0,%1,%2,%3},{%4,%5,%6,%7},{%8,%9},{%0,%1,%2,%3};"
        : "+f"(c[0]), "+f"(c[1]), "+f"(c[2]), "+f"(c[3])
        : "r"(a[0]), "r"(a[1]), "r"(a[2]), "r"(a[3]), "r"(b0), "r"(b1));
}

// ---------------- dtype probe -----------------------------------------------
__global__ void k_probe(const int* __restrict__ ei32) {
    __shared__ int anyNZ;
    if (threadIdx.x == 0) anyNZ = 0;
    __syncthreads();
    int nz = 0;
    #pragma unroll
    for (int i = 0; i < 8; i++) {
        int idx = 2 * (threadIdx.x + 256 * i) + 1;
        if (ei32[idx] != 0) nz = 1;
    }
    if (nz) atomicOr(&anyNZ, 1);
    __syncthreads();
    if (threadIdx.x == 0) g_is64 = anyNZ ? 0 : 1;
}

__device__ __forceinline__ int edge_at(const void* ei, long long idx) {
    if (g_is64) return (int)((const long long*)ei)[idx];
    return ((const int*)ei)[idx];
}

// ---------------- graph build ------------------------------------------------
__global__ void k_zero() {
    int i = blockIdx.x * blockDim.x + threadIdx.x;
    if (i < N_NODES) { g_deg[i] = 0; g_cur[i] = 0; }
}

__global__ void k_count(const void* __restrict__ ei) {
    int e = blockIdx.x * blockDim.x + threadIdx.x;
    if (e < N_EDGES) {
        int c = edge_at(ei, (long long)N_EDGES + e);
        if ((unsigned)c < N_NODES) atomicAdd(&g_deg[c], 1);
    }
}

__global__ void k_blocksum() {
    __shared__ int sh[256];
    int t = threadIdx.x;
    int i = blockIdx.x * 256 + t;
    int d = (i < N_NODES) ? g_deg[i] : 0;
    sh[t] = d;
    __syncthreads();
    #pragma unroll
    for (int off = 128; off > 0; off >>= 1) {
        if (t < off) sh[t] += sh[t + off];
        __syncthreads();
    }
    if (t == 0) g_bsum[blockIdx.x] = sh[0];
}

__global__ void k_scanb() {
    __shared__ int sh[512];
    int t = threadIdx.x;
    int v = (t < NBLK) ? g_bsum[t] : 0;
    sh[t] = v;
    __syncthreads();
    #pragma unroll
    for (int off = 1; off < 512; off <<= 1) {
        int u = (t >= off) ? sh[t - off] : 0;
        __syncthreads();
        sh[t] += u;
        __syncthreads();
    }
    if (t < NBLK) g_bsum[t] = sh[t] - v;
}

__global__ void k_offsets() {
    __shared__ int sh[256];
    int t = threadIdx.x;
    int i = blockIdx.x * 256 + t;
    int d = (i < N_NODES) ? g_deg[i] : 0;
    sh[t] = d;
    __syncthreads();
    #pragma unroll
    for (int off = 1; off < 256; off <<= 1) {
        int u = (t >= off) ? sh[t - off] : 0;
        __syncthreads();
        sh[t] += u;
        __syncthreads();
    }
    if (i < N_NODES) {
        g_off[i] = g_bsum[blockIdx.x] + sh[t] - d;
        g_dinv[i] = rsqrtf((float)(d + 1));
    }
    if (i == 0) g_off[N_NODES] = N_EDGES;
}

__global__ void k_fill(const void* __restrict__ ei) {
    int e = blockIdx.x * blockDim.x + threadIdx.x;
    if (e < N_EDGES) {
        int r = edge_at(ei, e);
        int c = edge_at(ei, (long long)N_EDGES + e);
        if ((unsigned)r >= N_NODES || (unsigned)c >= N_NODES) return;
        int pos = g_off[c] + atomicAdd(&g_cur[c], 1);
        if ((unsigned)pos < N_EDGES) g_src[pos] = r;
    }
}

// ---------------- mma.sync tf32 GEMM -----------------------------------------
// g_buf0[m][n] = dinv[m] * sum_k X[m][k] W[k][n]
// 3-term tf32 compensation: Ahi*Whi + Alo*Whi + Ahi*Wlo (err ~2^-22).
// 8 warps; warp w owns output cols [16w, 16w+16). W frags in registers.
// X staged in smem in fragment order: 64-row slabs, full K.
__global__ void __launch_bounds__(256) k_mgemm(const float* __restrict__ Xext,
                                               const float* __restrict__ W,
                                               int srcSel) {
    __shared__ float sX[64 * 128];     // fragment-order slab, 32 KB

    const float* X = srcSel ? g_buf1 : Xext;
    float*       Y = g_buf0;

    int tid = threadIdx.x, wid = tid >> 5, lane = tid & 31;
    int nbase = wid * 16;

    // ---- W fragments (hi+lo), registers, once per CTA ----
    uint32_t Whi[16][2][2], Wlo[16][2][2];
    #pragma unroll
    for (int ks = 0; ks < 16; ks++) {
        #pragma unroll
        for (int nb = 0; nb < 2; nb++) {
            int kr  = ks * 8 + (lane & 3);
            int col = nbase + nb * 8 + (lane >> 2);
            float w0 = W[kr * 128 + col];          // b0: k = lane%4
            float w1 = W[(kr + 4) * 128 + col];    // b1: k = lane%4 + 4
            uint32_t h0 = f2tf32(w0), h1 = f2tf32(w1);
            Whi[ks][nb][0] = h0;
            Whi[ks][nb][1] = h1;
            Wlo[ks][nb][0] = f2tf32(w0 - __uint_as_float(h0));
            Wlo[ks][nb][1] = f2tf32(w1 - __uint_as_float(h1));
        }
    }

    int rowBase = blockIdx.x * 128;
    const float4* Xv = (const float4*)X;

    #pragma unroll 1
    for (int slab = 0; slab < 2; slab++) {
        // ---- fill slab in fragment order ----
        #pragma unroll
        for (int i = 0; i < 8; i++) {
            int lin = tid + 256 * i;           // 2048 float4
            int rl = lin >> 5;                 // local row 0..63
            int kq = lin & 31;                 // float4 index in row
            int gr = rowBase + slab * 64 + rl;
            float4 v = (gr < N_NODES) ? Xv[(size_t)gr * 32 + kq]
                                      : make_float4(0.f, 0.f, 0.f, 0.f);
            int mb = rl >> 4, r = rl & 15;
            int k0 = kq * 4, ks = k0 >> 3;
            int base = (mb * 16 + ks) * 128 + (r & 7) * 16
                     + (r >> 3) + ((k0 & 4) ? 2 : 0);
            sX[base + 0]  = v.x;
            sX[base + 4]  = v.y;
            sX[base + 8]  = v.z;
            sX[base + 12] = v.w;
        }
        __syncthreads();

        // ---- compute 4 m-blocks of this slab ----
        #pragma unroll 1
        for (int mb = 0; mb < 4; mb++) {
            float acc[2][4];
            #pragma unroll
            for (int nb = 0; nb < 2; nb++)
                #pragma unroll
                for (int j = 0; j < 4; j++) acc[nb][j] = 0.f;

            #pragma unroll
            for (int ks = 0; ks < 16; ks++) {
                float4 a = *(const float4*)&sX[(mb * 16 + ks) * 128 + lane * 4];
                uint32_t ah[4], al[4];
                ah[0] = f2tf32(a.x); al[0] = f2tf32(a.x - __uint_as_float(ah[0]));
                ah[1] = f2tf32(a.y); al[1] = f2tf32(a.y - __uint_as_float(ah[1]));
                ah[2] = f2tf32(a.z); al[2] = f2tf32(a.z - __uint_as_float(ah[2]));
                ah[3] = f2tf32(a.w); al[3] = f2tf32(a.w - __uint_as_float(ah[3]));
                #pragma unroll
                for (int nb = 0; nb < 2; nb++) {
                    mma_tf32(acc[nb], ah, Whi[ks][nb][0], Whi[ks][nb][1]);
                    mma_tf32(acc[nb], al, Whi[ks][nb][0], Whi[ks][nb][1]);
                    mma_tf32(acc[nb], ah, Wlo[ks][nb][0], Wlo[ks][nb][1]);
                }
            }

            // ---- epilogue: scale by dinv, store ----
            int r0 = rowBase + slab * 64 + mb * 16 + (lane >> 2);
            int r1 = r0 + 8;
            float d0 = (r0 < N_NODES) ? g_dinv[r0] : 0.f;
            float d1 = (r1 < N_NODES) ? g_dinv[r1] : 0.f;
            #pragma unroll
            for (int nb = 0; nb < 2; nb++) {
                int cc = nbase + nb * 8 + (lane & 3) * 2;
                if (r0 < N_NODES) {
                    float2 o = make_float2(acc[nb][0] * d0, acc[nb][1] * d0);
                    *(float2*)&Y[(size_t)r0 * 128 + cc] = o;
                }
                if (r1 < N_NODES) {
                    float2 o = make_float2(acc[nb][2] * d1, acc[nb][3] * d1);
                    *(float2*)&Y[(size_t)r1 * 128 + cc] = o;
                }
            }
        }
        __syncthreads();
    }
}

// ---------------- aggregation: pure gather over dinv-scaled rows ------------
// buf0 = xts = dinv.*xt; out[c] = dinv[c]*(xts[c] + sum_in xts[s]) + bias
__global__ void __launch_bounds__(256) k_agg(const float* __restrict__ bias,
                                             float* __restrict__ outExt,
                                             int useExtOut) {
    int gw = (blockIdx.x * blockDim.x + threadIdx.x) >> 5;
    int lane = threadIdx.x & 31;
    if (gw >= N_NODES) return;
    int c = gw;

    const float4* xv = (const float4*)g_buf0;
    float*        out = useExtOut ? outExt : g_buf1;

    float4 acc = xv[(size_t)c * 32 + lane];     // self term

    int e0 = g_off[c], e1 = g_off[c + 1];
    int e = e0;
    for (; e + 4 <= e1; e += 4) {
        int s0 = __ldg(&g_src[e]);
        int s1 = __ldg(&g_src[e + 1]);
        int s2 = __ldg(&g_src[e + 2]);
        int s3 = __ldg(&g_src[e + 3]);
        float4 v0 = xv[(size_t)s0 * 32 + lane];
        float4 v1 = xv[(size_t)s1 * 32 + lane];
        float4 v2 = xv[(size_t)s2 * 32 + lane];
        float4 v3 = xv[(size_t)s3 * 32 + lane];
        acc.x += v0.x + v1.x + v2.x + v3.x;
        acc.y += v0.y + v1.y + v2.y + v3.y;
        acc.z += v0.z + v1.z + v2.z + v3.z;
        acc.w += v0.w + v1.w + v2.w + v3.w;
    }
    for (; e < e1; e++) {
        int s = __ldg(&g_src[e]);
        float4 v = xv[(size_t)s * 32 + lane];
        acc.x += v.x; acc.y += v.y; acc.z += v.z; acc.w += v.w;
    }

    float dc = g_dinv[c];
    float4 b = ((const float4*)bias)[lane];
    acc.x = acc.x * dc + b.x; acc.y = acc.y * dc + b.y;
    acc.z = acc.z * dc + b.z; acc.w = acc.w * dc + b.w;
    ((float4*)out)[(size_t)c * 32 + lane] = acc;
}

// ---------------- launch -----------------------------------------------------
extern "C" void kernel_launch(void* const* d_in, const int* in_sizes, int n_in,
                              void* d_out, int out_size) {
    const float* X  = (const float*)d_in[0];
    const void*  EI = d_in[1];
    const float* W1 = (const float*)d_in[2];
    const float* B1 = (const float*)d_in[3];
    const float* W2 = (const float*)d_in[4];
    const float* B2 = (const float*)d_in[5];
    float*       out = (float*)d_out;

    const int edgeBlocks = (N_EDGES + 255) / 256;
    const int aggBlocks  = (N_NODES * 32 + 255) / 256;

    // build CSC (by destination) + dinv
    k_probe<<<1, 256>>>((const int*)EI);
    k_zero<<<NBLK, 256>>>();
    k_count<<<edgeBlocks, 256>>>(EI);
    k_blocksum<<<NBLK, 256>>>();
    k_scanb<<<1, 512>>>();
    k_offsets<<<NBLK, 256>>>();
    k_fill<<<edgeBlocks, 256>>>(EI);

    // layer 1
    k_mgemm<<<N_TILES, 256>>>(X, W1, /*src=*/0);         // xts -> buf0
    k_agg<<<aggBlocks, 256>>>(B1, out, /*useExtOut=*/0); // h -> buf1

    // layer 2
    k_mgemm<<<N_TILES, 256>>>(nullptr, W2, /*src=*/1);   // xts -> buf0
    k_agg<<<aggBlocks, 256>>>(B2, out, /*useExtOut=*/1); // -> d_out
}

// round 7
// speedup vs baseline: 1.0983x; 1.0983x over previous
#include <cuda_runtime.h>
#include <cstdint>

#define N_NODES 100000
#define N_EDGES 1600000
#define HID 128
#define NBLK ((N_NODES + 255) / 256)     // 391
#define N_TILES ((N_NODES + 127) / 128)  // 782

// ---------------- scratch ----------------------------------------------------
__device__ __align__(16) float g_buf0[(size_t)N_NODES * HID]; // xts = dinv.*(X@W)
__device__ __align__(16) float g_buf1[(size_t)N_NODES * HID]; // layer-1 hidden
__device__ float g_dinv[N_NODES];
__device__ int   g_deg[N_NODES];
__device__ int   g_cur[N_NODES];
__device__ int   g_off[N_NODES + 1];
__device__ int   g_src[N_EDGES];
__device__ int   g_bsum[NBLK + 1];
__device__ int   g_is64;

// ---------------- helpers ----------------------------------------------------
__device__ __forceinline__ uint32_t f2tf32(float f) {
    uint32_t r;
    asm("cvt.rna.tf32.f32 %0, %1;" : "=r"(r) : "f"(f));
    return r;
}

__device__ __forceinline__ void mma_tf32(float c[4], uint32_t a0, uint32_t a1,
                                         uint32_t a2, uint32_t a3,
                                         uint32_t b0, uint32_t b1) {
    asm("mma.sync.aligned.m16n8k8.row.col.f32.tf32.tf32.f32 "
        "{%0,%1,%2,%3},{%4,%5,%6,%7},{%8,%9},{%0,%1,%2,%3};"
        : "+f"(c[0]), "+f"(c[1]), "+f"(c[2]), "+f"(c[3])
        : "r"(a0), "r"(a1), "r"(a2), "r"(a3), "r"(b0), "r"(b1));
}

// ---------------- dtype probe -----------------------------------------------
__global__ void k_probe(const int* __restrict__ ei32) {
    __shared__ int anyNZ;
    if (threadIdx.x == 0) anyNZ = 0;
    __syncthreads();
    int nz = 0;
    #pragma unroll
    for (int i = 0; i < 8; i++) {
        int idx = 2 * (threadIdx.x + 256 * i) + 1;
        if (ei32[idx] != 0) nz = 1;
    }
    if (nz) atomicOr(&anyNZ, 1);
    __syncthreads();
    if (threadIdx.x == 0) g_is64 = anyNZ ? 0 : 1;
}

__device__ __forceinline__ int edge_at(const void* ei, long long idx) {
    if (g_is64) return (int)((const long long*)ei)[idx];
    return ((const int*)ei)[idx];
}

// ---------------- graph build ------------------------------------------------
__global__ void k_zero() {
    int i = blockIdx.x * blockDim.x + threadIdx.x;
    if (i < N_NODES) { g_deg[i] = 0; g_cur[i] = 0; }
}

__global__ void k_count(const void* __restrict__ ei) {
    int e = blockIdx.x * blockDim.x + threadIdx.x;
    if (e < N_EDGES) {
        int c = edge_at(ei, (long long)N_EDGES + e);
        if ((unsigned)c < N_NODES) atomicAdd(&g_deg[c], 1);
    }
}

__global__ void k_blocksum() {
    __shared__ int sh[256];
    int t = threadIdx.x;
    int i = blockIdx.x * 256 + t;
    int d = (i < N_NODES) ? g_deg[i] : 0;
    sh[t] = d;
    __syncthreads();
    #pragma unroll
    for (int off = 128; off > 0; off >>= 1) {
        if (t < off) sh[t] += sh[t + off];
        __syncthreads();
    }
    if (t == 0) g_bsum[blockIdx.x] = sh[0];
}

__global__ void k_scanb() {
    __shared__ int sh[512];
    int t = threadIdx.x;
    int v = (t < NBLK) ? g_bsum[t] : 0;
    sh[t] = v;
    __syncthreads();
    #pragma unroll
    for (int off = 1; off < 512; off <<= 1) {
        int u = (t >= off) ? sh[t - off] : 0;
        __syncthreads();
        sh[t] += u;
        __syncthreads();
    }
    if (t < NBLK) g_bsum[t] = sh[t] - v;
}

__global__ void k_offsets() {
    __shared__ int sh[256];
    int t = threadIdx.x;
    int i = blockIdx.x * 256 + t;
    int d = (i < N_NODES) ? g_deg[i] : 0;
    sh[t] = d;
    __syncthreads();
    #pragma unroll
    for (int off = 1; off < 256; off <<= 1) {
        int u = (t >= off) ? sh[t - off] : 0;
        __syncthreads();
        sh[t] += u;
        __syncthreads();
    }
    if (i < N_NODES) {
        g_off[i] = g_bsum[blockIdx.x] + sh[t] - d;
        g_dinv[i] = rsqrtf((float)(d + 1));
    }
    if (i == 0) g_off[N_NODES] = N_EDGES;
}

__global__ void k_fill(const void* __restrict__ ei) {
    int e = blockIdx.x * blockDim.x + threadIdx.x;
    if (e < N_EDGES) {
        int r = edge_at(ei, e);
        int c = edge_at(ei, (long long)N_EDGES + e);
        if ((unsigned)r >= N_NODES || (unsigned)c >= N_NODES) return;
        int pos = g_off[c] + atomicAdd(&g_cur[c], 1);
        if ((unsigned)pos < N_EDGES) g_src[pos] = r;
    }
}

// ---------------- mma.sync tf32 GEMM (hi/lo precomputed in smem) -------------
// g_buf0[m][n] = dinv[m] * sum_k X[m][k] W[k][n]
// 3-term: Ahi*Whi + Alo*Whi + Ahi*Wlo. 8 warps split N (16 cols each).
// X staged per 32-row slab as PRE-CONVERTED tf32 hi/lo fragments (XOR-swizzled).
__global__ void __launch_bounds__(256) k_mgemm(const float* __restrict__ Xext,
                                               const float* __restrict__ W,
                                               int srcSel) {
    __shared__ uint32_t sHi[32 * 128];   // 16 KB, fragment order
    __shared__ uint32_t sLo[32 * 128];   // 16 KB

    const float* X = srcSel ? g_buf1 : Xext;
    float*       Y = g_buf0;

    int tid = threadIdx.x, wid = tid >> 5, lane = tid & 31;
    int nbase = wid * 16;

    // ---- W fragments (hi+lo) in registers, once per CTA ----
    uint32_t Whi[16][2][2], Wlo[16][2][2];
    #pragma unroll
    for (int ks = 0; ks < 16; ks++) {
        #pragma unroll
        for (int nb = 0; nb < 2; nb++) {
            int kr  = ks * 8 + (lane & 3);
            int col = nbase + nb * 8 + (lane >> 2);
            float w0 = W[kr * 128 + col];
            float w1 = W[(kr + 4) * 128 + col];
            uint32_t h0 = f2tf32(w0), h1 = f2tf32(w1);
            Whi[ks][nb][0] = h0;
            Whi[ks][nb][1] = h1;
            Wlo[ks][nb][0] = f2tf32(w0 - __uint_as_float(h0));
            Wlo[ks][nb][1] = f2tf32(w1 - __uint_as_float(h1));
        }
    }

    int rowBase = blockIdx.x * 128;
    const float4* Xv = (const float4*)X;

    // prefetch slab 0
    float4 pv[4];
    #pragma unroll
    for (int i = 0; i < 4; i++) {
        int lin = tid + 256 * i;
        int rl = lin >> 5, kq = lin & 31;
        int gr = rowBase + rl;
        pv[i] = (gr < N_NODES) ? Xv[(size_t)gr * 32 + kq]
                               : make_float4(0.f, 0.f, 0.f, 0.f);
    }

    #pragma unroll 1
    for (int slab = 0; slab < 4; slab++) {
        __syncthreads();   // previous compute done reading smem

        // ---- store prefetched slab as tf32 hi/lo fragments ----
        #pragma unroll
        for (int i = 0; i < 4; i++) {
            int lin = lin = tid + 256 * i;
            int rl = lin >> 5, kq = lin & 31;
            int mb = rl >> 4;
            int frag = mb * 16 + (kq >> 1);
            int jb = ((rl >> 3) & 1) + ((kq & 1) << 1);
            int slbase = ((rl & 7) ^ (frag & 7)) << 2;
            int base = frag * 128 + slbase * 4 + jb;
            float4 v = pv[i];
            uint32_t h, l;
            h = f2tf32(v.x); l = f2tf32(v.x - __uint_as_float(h));
            sHi[base + 0]  = h; sLo[base + 0]  = l;
            h = f2tf32(v.y); l = f2tf32(v.y - __uint_as_float(h));
            sHi[base + 4]  = h; sLo[base + 4]  = l;
            h = f2tf32(v.z); l = f2tf32(v.z - __uint_as_float(h));
            sHi[base + 8]  = h; sLo[base + 8]  = l;
            h = f2tf32(v.w); l = f2tf32(v.w - __uint_as_float(h));
            sHi[base + 12] = h; sLo[base + 12] = l;
        }
        __syncthreads();

        // ---- prefetch next slab while computing ----
        if (slab < 3) {
            #pragma unroll
            for (int i = 0; i < 4; i++) {
                int lin = tid + 256 * i;
                int rl = lin >> 5, kq = lin & 31;
                int gr = rowBase + (slab + 1) * 32 + rl;
                pv[i] = (gr < N_NODES) ? Xv[(size_t)gr * 32 + kq]
                                       : make_float4(0.f, 0.f, 0.f, 0.f);
            }
        }

        // ---- compute 2 m-blocks of this slab ----
        #pragma unroll 1
        for (int mb = 0; mb < 2; mb++) {
            float acc[2][4];
            #pragma unroll
            for (int nb = 0; nb < 2; nb++)
                #pragma unroll
                for (int j = 0; j < 4; j++) acc[nb][j] = 0.f;

            #pragma unroll
            for (int ks = 0; ks < 16; ks++) {
                int f = mb * 16 + ks;
                int idx = f * 128 + (lane ^ ((ks & 7) << 2)) * 4;
                uint4 ah = *(const uint4*)&sHi[idx];
                uint4 al = *(const uint4*)&sLo[idx];
                #pragma unroll
                for (int nb = 0; nb < 2; nb++) {
                    mma_tf32(acc[nb], ah.x, ah.y, ah.z, ah.w,
                             Whi[ks][nb][0], Whi[ks][nb][1]);
                    mma_tf32(acc[nb], al.x, al.y, al.z, al.w,
                             Whi[ks][nb][0], Whi[ks][nb][1]);
                    mma_tf32(acc[nb], ah.x, ah.y, ah.z, ah.w,
                             Wlo[ks][nb][0], Wlo[ks][nb][1]);
                }
            }

            // ---- epilogue: scale by dinv, store ----
            int r0 = rowBase + slab * 32 + mb * 16 + (lane >> 2);
            int r1 = r0 + 8;
            float d0 = (r0 < N_NODES) ? g_dinv[r0] : 0.f;
            float d1 = (r1 < N_NODES) ? g_dinv[r1] : 0.f;
            #pragma unroll
            for (int nb = 0; nb < 2; nb++) {
                int cc = nbase + nb * 8 + (lane & 3) * 2;
                if (r0 < N_NODES) {
                    float2 o = make_float2(acc[nb][0] * d0, acc[nb][1] * d0);
                    *(float2*)&Y[(size_t)r0 * 128 + cc] = o;
                }
                if (r1 < N_NODES) {
                    float2 o = make_float2(acc[nb][2] * d1, acc[nb][3] * d1);
                    *(float2*)&Y[(size_t)r1 * 128 + cc] = o;
                }
            }
        }
    }
}

// ---------------- aggregation: pure gather over dinv-scaled rows ------------
// buf0 = xts = dinv.*xt; out[c] = dinv[c]*(xts[c] + sum_in xts[s]) + bias
__global__ void __launch_bounds__(256) k_agg(const float* __restrict__ bias,
                                             float* __restrict__ outExt,
                                             int useExtOut) {
    int gw = (blockIdx.x * blockDim.x + threadIdx.x) >> 5;
    int lane = threadIdx.x & 31;
    if (gw >= N_NODES) return;
    int c = gw;

    const float4* xv = (const float4*)g_buf0;
    float*        out = useExtOut ? outExt : g_buf1;

    float4 acc = xv[(size_t)c * 32 + lane];     // self term

    int e0 = g_off[c], e1 = g_off[c + 1];
    int e = e0;
    for (; e + 4 <= e1; e += 4) {
        int s0 = __ldg(&g_src[e]);
        int s1 = __ldg(&g_src[e + 1]);
        int s2 = __ldg(&g_src[e + 2]);
        int s3 = __ldg(&g_src[e + 3]);
        float4 v0 = xv[(size_t)s0 * 32 + lane];
        float4 v1 = xv[(size_t)s1 * 32 + lane];
        float4 v2 = xv[(size_t)s2 * 32 + lane];
        float4 v3 = xv[(size_t)s3 * 32 + lane];
        acc.x += v0.x + v1.x + v2.x + v3.x;
        acc.y += v0.y + v1.y + v2.y + v3.y;
        acc.z += v0.z + v1.z + v2.z + v3.z;
        acc.w += v0.w + v1.w + v2.w + v3.w;
    }
    for (; e < e1; e++) {
        int s = __ldg(&g_src[e]);
        float4 v = xv[(size_t)s * 32 + lane];
        acc.x += v.x; acc.y += v.y; acc.z += v.z; acc.w += v.w;
    }

    float dc = g_dinv[c];
    float4 b = ((const float4*)bias)[lane];
    acc.x = acc.x * dc + b.x; acc.y = acc.y * dc + b.y;
    acc.z = acc.z * dc + b.z; acc.w = acc.w * dc + b.w;
    ((float4*)out)[(size_t)c * 32 + lane] = acc;
}

// ---------------- launch -----------------------------------------------------
extern "C" void kernel_launch(void* const* d_in, const int* in_sizes, int n_in,
                              void* d_out, int out_size) {
    const float* X  = (const float*)d_in[0];
    const void*  EI = d_in[1];
    const float* W1 = (const float*)d_in[2];
    const float* B1 = (const float*)d_in[3];
    const float* W2 = (const float*)d_in[4];
    const float* B2 = (const float*)d_in[5];
    float*       out = (float*)d_out;

    const int edgeBlocks = (N_EDGES + 255) / 256;
    const int aggBlocks  = (N_NODES * 32 + 255) / 256;

    // build CSC (by destination) + dinv
    k_probe<<<1, 256>>>((const int*)EI);
    k_zero<<<NBLK, 256>>>();
    k_count<<<edgeBlocks, 256>>>(EI);
    k_blocksum<<<NBLK, 256>>>();
    k_scanb<<<1, 512>>>();
    k_offsets<<<NBLK, 256>>>();
    k_fill<<<edgeBlocks, 256>>>(EI);

    // layer 1
    k_mgemm<<<N_TILES, 256>>>(X, W1, /*src=*/0);         // xts -> buf0
    k_agg<<<aggBlocks, 256>>>(B1, out, /*useExtOut=*/0); // h -> buf1

    // layer 2
    k_mgemm<<<N_TILES, 256>>>(nullptr, W2, /*src=*/1);   // xts -> buf0
    k_agg<<<aggBlocks, 256>>>(B2, out, /*useExtOut=*/1); // -> d_out
}

// round 8
// speedup vs baseline: 1.6979x; 1.5459x over previous
#include <cuda_runtime.h>
#include <cuda_bf16.h>
#include <cstdint>

#define N_NODES 100000
#define N_EDGES 1600000
#define HID 128
#define NBLK ((N_NODES + 255) / 256)     // 391
#define N_TILES ((N_NODES + 127) / 128)  // 782

// ---------------- scratch ----------------------------------------------------
__device__ __align__(16) float g_buf0[(size_t)N_NODES * HID]; // xts = dinv.*(X@W)
__device__ __align__(16) float g_buf1[(size_t)N_NODES * HID]; // layer-1 hidden
__device__ float g_dinv[N_NODES];
__device__ int   g_deg[N_NODES];
__device__ int   g_cur[N_NODES];
__device__ int   g_off[N_NODES + 1];
__device__ int   g_src[N_EDGES];
__device__ int   g_bsum[NBLK + 1];
__device__ int   g_is64;

// ---------------- helpers ----------------------------------------------------
// pack two floats to bf16x2 (lo = first arg, hi = second)
__device__ __forceinline__ uint32_t pack_bf16(float lo, float hi) {
    uint32_t r;
    asm("cvt.rn.bf16x2.f32 %0, %1, %2;" : "=r"(r) : "f"(hi), "f"(lo));
    return r;
}
__device__ __forceinline__ float bf16_round(float v) {
    __nv_bfloat16 h = __float2bfloat16_rn(v);
    return __bfloat162float(h);
}

__device__ __forceinline__ void mma_bf16(float c[4], uint32_t a0, uint32_t a1,
                                         uint32_t a2, uint32_t a3,
                                         uint32_t b0, uint32_t b1) {
    asm("mma.sync.aligned.m16n8k16.row.col.f32.bf16.bf16.f32 "
        "{%0,%1,%2,%3},{%4,%5,%6,%7},{%8,%9},{%0,%1,%2,%3};"
        : "+f"(c[0]), "+f"(c[1]), "+f"(c[2]), "+f"(c[3])
        : "r"(a0), "r"(a1), "r"(a2), "r"(a3), "r"(b0), "r"(b1));
}

// ---------------- dtype probe -----------------------------------------------
__global__ void k_probe(const int* __restrict__ ei32) {
    __shared__ int anyNZ;
    if (threadIdx.x == 0) anyNZ = 0;
    __syncthreads();
    int nz = 0;
    #pragma unroll
    for (int i = 0; i < 8; i++) {
        int idx = 2 * (threadIdx.x + 256 * i) + 1;
        if (ei32[idx] != 0) nz = 1;
    }
    if (nz) atomicOr(&anyNZ, 1);
    __syncthreads();
    if (threadIdx.x == 0) g_is64 = anyNZ ? 0 : 1;
}

__device__ __forceinline__ int edge_at(const void* ei, long long idx) {
    if (g_is64) return (int)((const long long*)ei)[idx];
    return ((const int*)ei)[idx];
}

// ---------------- graph build ------------------------------------------------
__global__ void k_zero() {
    int i = blockIdx.x * blockDim.x + threadIdx.x;
    if (i < N_NODES) { g_deg[i] = 0; g_cur[i] = 0; }
}

__global__ void k_count(const void* __restrict__ ei) {
    int e = blockIdx.x * blockDim.x + threadIdx.x;
    if (e < N_EDGES) {
        int c = edge_at(ei, (long long)N_EDGES + e);
        if ((unsigned)c < N_NODES) atomicAdd(&g_deg[c], 1);
    }
}

__global__ void k_blocksum() {
    __shared__ int sh[256];
    int t = threadIdx.x;
    int i = blockIdx.x * 256 + t;
    int d = (i < N_NODES) ? g_deg[i] : 0;
    sh[t] = d;
    __syncthreads();
    #pragma unroll
    for (int off = 128; off > 0; off >>= 1) {
        if (t < off) sh[t] += sh[t + off];
        __syncthreads();
    }
    if (t == 0) g_bsum[blockIdx.x] = sh[0];
}

__global__ void k_scanb() {
    __shared__ int sh[512];
    int t = threadIdx.x;
    int v = (t < NBLK) ? g_bsum[t] : 0;
    sh[t] = v;
    __syncthreads();
    #pragma unroll
    for (int off = 1; off < 512; off <<= 1) {
        int u = (t >= off) ? sh[t - off] : 0;
        __syncthreads();
        sh[t] += u;
        __syncthreads();
    }
    if (t < NBLK) g_bsum[t] = sh[t] - v;
}

__global__ void k_offsets() {
    __shared__ int sh[256];
    int t = threadIdx.x;
    int i = blockIdx.x * 256 + t;
    int d = (i < N_NODES) ? g_deg[i] : 0;
    sh[t] = d;
    __syncthreads();
    #pragma unroll
    for (int off = 1; off < 256; off <<= 1) {
        int u = (t >= off) ? sh[t - off] : 0;
        __syncthreads();
        sh[t] += u;
        __syncthreads();
    }
    if (i < N_NODES) {
        g_off[i] = g_bsum[blockIdx.x] + sh[t] - d;
        g_dinv[i] = rsqrtf((float)(d + 1));
    }
    if (i == 0) g_off[N_NODES] = N_EDGES;
}

__global__ void k_fill(const void* __restrict__ ei) {
    int e = blockIdx.x * blockDim.x + threadIdx.x;
    if (e < N_EDGES) {
        int r = edge_at(ei, e);
        int c = edge_at(ei, (long long)N_EDGES + e);
        if ((unsigned)r >= N_NODES || (unsigned)c >= N_NODES) return;
        int pos = g_off[c] + atomicAdd(&g_cur[c], 1);
        if ((unsigned)pos < N_EDGES) g_src[pos] = r;
    }
}

// ---------------- bf16 3-term mma.sync GEMM ----------------------------------
// g_buf0[m][n] = dinv[m] * sum_k X[m][k] W[k][n]
// x = xhi + xlo (bf16 split); D = Ahi*Whi + Alo*Whi + Ahi*Wlo (err ~2^-18).
// 8 warps split N (16 cols each). W frags (hi+lo) in regs (64).
// X staged per 32-row slab as packed bf16x2 fragments, XOR-swizzled.
__global__ void __launch_bounds__(256) k_mgemm(const float* __restrict__ Xext,
                                               const float* __restrict__ W,
                                               int srcSel) {
    __shared__ uint32_t sHi[16 * 128];   // 16 frags x 128 u32 = 8 KB
    __shared__ uint32_t sLo[16 * 128];   // 8 KB

    const float* X = srcSel ? g_buf1 : Xext;
    float*       Y = g_buf0;

    int tid = threadIdx.x, wid = tid >> 5, lane = tid & 31;
    int nbase = wid * 16;

    // ---- W fragments (hi+lo) in registers, once per CTA ----
    // m16n8k16 B frag: b0: k=(lane&3)*2+{0,1}, n=lane>>2 ; b1: k+8
    uint32_t Whi[8][2][2], Wlo[8][2][2];
    #pragma unroll
    for (int ks = 0; ks < 8; ks++) {
        #pragma unroll
        for (int nb = 0; nb < 2; nb++) {
            int col = nbase + nb * 8 + (lane >> 2);
            int k0  = ks * 16 + (lane & 3) * 2;
            float w00 = W[(k0 + 0) * 128 + col];
            float w01 = W[(k0 + 1) * 128 + col];
            float w10 = W[(k0 + 8) * 128 + col];
            float w11 = W[(k0 + 9) * 128 + col];
            float h00 = bf16_round(w00), h01 = bf16_round(w01);
            float h10 = bf16_round(w10), h11 = bf16_round(w11);
            Whi[ks][nb][0] = pack_bf16(h00, h01);
            Whi[ks][nb][1] = pack_bf16(h10, h11);
            Wlo[ks][nb][0] = pack_bf16(w00 - h00, w01 - h01);
            Wlo[ks][nb][1] = pack_bf16(w10 - h10, w11 - h11);
        }
    }

    int rowBase = blockIdx.x * 128;
    const float4* Xv = (const float4*)X;

    // prefetch slab 0 (32 rows x 128 cols = 1024 float4)
    float4 pv[4];
    #pragma unroll
    for (int i = 0; i < 4; i++) {
        int lin = tid + 256 * i;
        int rl = lin >> 5, kq = lin & 31;
        int gr = rowBase + rl;
        pv[i] = (gr < N_NODES) ? Xv[(size_t)gr * 32 + kq]
                               : make_float4(0.f, 0.f, 0.f, 0.f);
    }

    #pragma unroll 1
    for (int slab = 0; slab < 4; slab++) {
        __syncthreads();   // previous compute done reading smem

        // ---- store slab as packed bf16x2 hi/lo fragments ----
        // A frag (m16n8k16): a0:(r,k) a1:(r+8,k) a2:(r,k+8) a3:(r+8,k+8),
        // k=(lane&3)*2+{0,1}; j = rbit + 2*kbit; slot = (r&7)*4 + (kloc&7)/2.
        #pragma unroll
        for (int i = 0; i < 4; i++) {
            int lin = tid + 256 * i;
            int rl = lin >> 5, kq = lin & 31;
            int mb = rl >> 4, rloc = rl & 15;
            int ks = kq >> 2;
            int k0 = 4 * kq;
            int j = ((rloc >> 3) & 1) + (((kq >> 1) & 1) << 1);
            int slot = (rloc & 7) * 4 + 2 * (kq & 1);
            int slot_sw = slot ^ (ks << 2);
            int base = (mb * 8 + ks) * 128 + slot_sw * 4 + j;
            float4 v = pv[i];
            float hx = bf16_round(v.x), hy = bf16_round(v.y);
            float hz = bf16_round(v.z), hw = bf16_round(v.w);
            sHi[base]     = pack_bf16(hx, hy);
            sHi[base + 4] = pack_bf16(hz, hw);
            sLo[base]     = pack_bf16(v.x - hx, v.y - hy);
            sLo[base + 4] = pack_bf16(v.z - hz, v.w - hw);
        }
        __syncthreads();

        // ---- prefetch next slab while computing ----
        if (slab < 3) {
            #pragma unroll
            for (int i = 0; i < 4; i++) {
                int lin = tid + 256 * i;
                int rl = lin >> 5, kq = lin & 31;
                int gr = rowBase + (slab + 1) * 32 + rl;
                pv[i] = (gr < N_NODES) ? Xv[(size_t)gr * 32 + kq]
                                       : make_float4(0.f, 0.f, 0.f, 0.f);
            }
        }

        // ---- compute 2 m-blocks of this slab ----
        #pragma unroll 1
        for (int mb = 0; mb < 2; mb++) {
            float a0[2][4], a1[2][4], a2[2][4];
            #pragma unroll
            for (int nb = 0; nb < 2; nb++)
                #pragma unroll
                for (int j = 0; j < 4; j++) { a0[nb][j] = 0.f; a1[nb][j] = 0.f; a2[nb][j] = 0.f; }

            #pragma unroll
            for (int ks = 0; ks < 8; ks++) {
                int idx = (mb * 8 + ks) * 128 + (lane ^ (ks << 2)) * 4;
                uint4 ah = *(const uint4*)&sHi[idx];
                uint4 al = *(const uint4*)&sLo[idx];
                #pragma unroll
                for (int nb = 0; nb < 2; nb++) {
                    mma_bf16(a0[nb], ah.x, ah.y, ah.z, ah.w,
                             Whi[ks][nb][0], Whi[ks][nb][1]);
                    mma_bf16(a1[nb], al.x, al.y, al.z, al.w,
                             Whi[ks][nb][0], Whi[ks][nb][1]);
                    mma_bf16(a2[nb], ah.x, ah.y, ah.z, ah.w,
                             Wlo[ks][nb][0], Wlo[ks][nb][1]);
                }
            }

            // ---- epilogue: combine terms, scale by dinv, store ----
            int r0 = rowBase + slab * 32 + mb * 16 + (lane >> 2);
            int r1 = r0 + 8;
            float d0 = (r0 < N_NODES) ? g_dinv[r0] : 0.f;
            float d1 = (r1 < N_NODES) ? g_dinv[r1] : 0.f;
            #pragma unroll
            for (int nb = 0; nb < 2; nb++) {
                int cc = nbase + nb * 8 + (lane & 3) * 2;
                float s0 = a0[nb][0] + a1[nb][0] + a2[nb][0];
                float s1 = a0[nb][1] + a1[nb][1] + a2[nb][1];
                float s2 = a0[nb][2] + a1[nb][2] + a2[nb][2];
                float s3 = a0[nb][3] + a1[nb][3] + a2[nb][3];
                if (r0 < N_NODES)
                    *(float2*)&Y[(size_t)r0 * 128 + cc] = make_float2(s0 * d0, s1 * d0);
                if (r1 < N_NODES)
                    *(float2*)&Y[(size_t)r1 * 128 + cc] = make_float2(s2 * d1, s3 * d1);
            }
        }
    }
}

// ---------------- aggregation: pure gather over dinv-scaled rows ------------
// buf0 = xts = dinv.*xt; out[c] = dinv[c]*(xts[c] + sum_in xts[s]) + bias
__global__ void __launch_bounds__(256) k_agg(const float* __restrict__ bias,
                                             float* __restrict__ outExt,
                                             int useExtOut) {
    int gw = (blockIdx.x * blockDim.x + threadIdx.x) >> 5;
    int lane = threadIdx.x & 31;
    if (gw >= N_NODES) return;
    int c = gw;

    const float4* xv = (const float4*)g_buf0;
    float*        out = useExtOut ? outExt : g_buf1;

    float4 acc = xv[(size_t)c * 32 + lane];     // self term

    int e0 = g_off[c], e1 = g_off[c + 1];
    int e = e0;
    for (; e + 4 <= e1; e += 4) {
        int s0 = __ldg(&g_src[e]);
        int s1 = __ldg(&g_src[e + 1]);
        int s2 = __ldg(&g_src[e + 2]);
        int s3 = __ldg(&g_src[e + 3]);
        float4 v0 = xv[(size_t)s0 * 32 + lane];
        float4 v1 = xv[(size_t)s1 * 32 + lane];
        float4 v2 = xv[(size_t)s2 * 32 + lane];
        float4 v3 = xv[(size_t)s3 * 32 + lane];
        acc.x += v0.x + v1.x + v2.x + v3.x;
        acc.y += v0.y + v1.y + v2.y + v3.y;
        acc.z += v0.z + v1.z + v2.z + v3.z;
        acc.w += v0.w + v1.w + v2.w + v3.w;
    }
    for (; e < e1; e++) {
        int s = __ldg(&g_src[e]);
        float4 v = xv[(size_t)s * 32 + lane];
        acc.x += v.x; acc.y += v.y; acc.z += v.z; acc.w += v.w;
    }

    float dc = g_dinv[c];
    float4 b = ((const float4*)bias)[lane];
    acc.x = acc.x * dc + b.x; acc.y = acc.y * dc + b.y;
    acc.z = acc.z * dc + b.z; acc.w = acc.w * dc + b.w;
    ((float4*)out)[(size_t)c * 32 + lane] = acc;
}

// ---------------- launch -----------------------------------------------------
extern "C" void kernel_launch(void* const* d_in, const int* in_sizes, int n_in,
                              void* d_out, int out_size) {
    const float* X  = (const float*)d_in[0];
    const void*  EI = d_in[1];
    const float* W1 = (const float*)d_in[2];
    const float* B1 = (const float*)d_in[3];
    const float* W2 = (const float*)d_in[4];
    const float* B2 = (const float*)d_in[5];
    float*       out = (float*)d_out;

    const int edgeBlocks = (N_EDGES + 255) / 256;
    const int aggBlocks  = (N_NODES * 32 + 255) / 256;

    // build CSC (by destination) + dinv
    k_probe<<<1, 256>>>((const int*)EI);
    k_zero<<<NBLK, 256>>>();
    k_count<<<edgeBlocks, 256>>>(EI);
    k_blocksum<<<NBLK, 256>>>();
    k_scanb<<<1, 512>>>();
    k_offsets<<<NBLK, 256>>>();
    k_fill<<<edgeBlocks, 256>>>(EI);

    // layer 1
    k_mgemm<<<N_TILES, 256>>>(X, W1, /*src=*/0);         // xts -> buf0
    k_agg<<<aggBlocks, 256>>>(B1, out, /*useExtOut=*/0); // h -> buf1

    // layer 2
    k_mgemm<<<N_TILES, 256>>>(nullptr, W2, /*src=*/1);   // xts -> buf0
    k_agg<<<aggBlocks, 256>>>(B2, out, /*useExtOut=*/1); // -> d_out
}

// round 9
// speedup vs baseline: 1.7732x; 1.0444x over previous
#include <cuda_runtime.h>
#include <cuda_bf16.h>
#include <cuda_fp16.h>
#include <cstdint>

#define N_NODES 100000
#define N_EDGES 1600000
#define HID 128
#define NBLK ((N_NODES + 255) / 256)     // 391
#define N_TILES ((N_NODES + 127) / 128)  // 782

// ---------------- scratch ----------------------------------------------------
__device__ __align__(16) __half2 g_h16[(size_t)N_NODES * 64]; // xts in fp16
__device__ __align__(16) float g_buf1[(size_t)N_NODES * HID]; // layer-1 hidden (fp32)
__device__ float g_dinv[N_NODES];
__device__ int   g_deg[N_NODES];
__device__ int   g_cur[N_NODES];
__device__ int   g_off[N_NODES + 1];
__device__ int   g_src[N_EDGES];
__device__ int   g_bsum[NBLK + 1];
__device__ int   g_is64;

// ---------------- helpers ----------------------------------------------------
__device__ __forceinline__ uint32_t pack_bf16(float lo, float hi) {
    uint32_t r;
    asm("cvt.rn.bf16x2.f32 %0, %1, %2;" : "=r"(r) : "f"(hi), "f"(lo));
    return r;
}
__device__ __forceinline__ float bf16_round(float v) {
    __nv_bfloat16 h = __float2bfloat16_rn(v);
    return __bfloat162float(h);
}

__device__ __forceinline__ void mma_bf16(float c[4], uint32_t a0, uint32_t a1,
                                         uint32_t a2, uint32_t a3,
                                         uint32_t b0, uint32_t b1) {
    asm("mma.sync.aligned.m16n8k16.row.col.f32.bf16.bf16.f32 "
        "{%0,%1,%2,%3},{%4,%5,%6,%7},{%8,%9},{%0,%1,%2,%3};"
        : "+f"(c[0]), "+f"(c[1]), "+f"(c[2]), "+f"(c[3])
        : "r"(a0), "r"(a1), "r"(a2), "r"(a3), "r"(b0), "r"(b1));
}

__device__ __forceinline__ float4 unpack4(uint2 u) {
    __half2 a = *(__half2*)&u.x, b = *(__half2*)&u.y;
    float2 fa = __half22float2(a), fb = __half22float2(b);
    return make_float4(fa.x, fa.y, fb.x, fb.y);
}

// ---------------- init: zero counters + dtype probe (block 0) ----------------
__global__ void k_init(const int* __restrict__ ei32) {
    int i = blockIdx.x * 256 + threadIdx.x;
    if (i < N_NODES) { g_deg[i] = 0; g_cur[i] = 0; }
    if (blockIdx.x == 0) {
        __shared__ int anyNZ;
        if (threadIdx.x == 0) anyNZ = 0;
        __syncthreads();
        int nz = 0;
        #pragma unroll
        for (int j = 0; j < 8; j++) {
            int idx = 2 * (threadIdx.x + 256 * j) + 1;   // odd words
            if (ei32[idx] != 0) nz = 1;
        }
        if (nz) atomicOr(&anyNZ, 1);
        __syncthreads();
        if (threadIdx.x == 0) g_is64 = anyNZ ? 0 : 1;
    }
}

__device__ __forceinline__ int edge_at(const void* ei, long long idx) {
    if (g_is64) return (int)((const long long*)ei)[idx];
    return ((const int*)ei)[idx];
}

// ---------------- graph build ------------------------------------------------
__global__ void k_count(const void* __restrict__ ei) {
    int e = blockIdx.x * blockDim.x + threadIdx.x;
    if (e < N_EDGES) {
        int c = edge_at(ei, (long long)N_EDGES + e);
        if ((unsigned)c < N_NODES) atomicAdd(&g_deg[c], 1);
    }
}

__global__ void k_blocksum() {
    __shared__ int sh[256];
    int t = threadIdx.x;
    int i = blockIdx.x * 256 + t;
    int d = (i < N_NODES) ? g_deg[i] : 0;
    sh[t] = d;
    __syncthreads();
    #pragma unroll
    for (int off = 128; off > 0; off >>= 1) {
        if (t < off) sh[t] += sh[t + off];
        __syncthreads();
    }
    if (t == 0) g_bsum[blockIdx.x] = sh[0];
}

__global__ void k_scanb() {
    __shared__ int sh[512];
    int t = threadIdx.x;
    int v = (t < NBLK) ? g_bsum[t] : 0;
    sh[t] = v;
    __syncthreads();
    #pragma unroll
    for (int off = 1; off < 512; off <<= 1) {
        int u = (t >= off) ? sh[t - off] : 0;
        __syncthreads();
        sh[t] += u;
        __syncthreads();
    }
    if (t < NBLK) g_bsum[t] = sh[t] - v;
}

__global__ void k_offsets() {
    __shared__ int sh[256];
    int t = threadIdx.x;
    int i = blockIdx.x * 256 + t;
    int d = (i < N_NODES) ? g_deg[i] : 0;
    sh[t] = d;
    __syncthreads();
    #pragma unroll
    for (int off = 1; off < 256; off <<= 1) {
        int u = (t >= off) ? sh[t - off] : 0;
        __syncthreads();
        sh[t] += u;
        __syncthreads();
    }
    if (i < N_NODES) {
        g_off[i] = g_bsum[blockIdx.x] + sh[t] - d;
        g_dinv[i] = rsqrtf((float)(d + 1));
    }
    if (i == 0) g_off[N_NODES] = N_EDGES;
}

__global__ void k_fill(const void* __restrict__ ei) {
    int e = blockIdx.x * blockDim.x + threadIdx.x;
    if (e < N_EDGES) {
        int r = edge_at(ei, e);
        int c = edge_at(ei, (long long)N_EDGES + e);
        if ((unsigned)r >= N_NODES || (unsigned)c >= N_NODES) return;
        int pos = g_off[c] + atomicAdd(&g_cur[c], 1);
        if ((unsigned)pos < N_EDGES) g_src[pos] = r;
    }
}

// ---------------- bf16 3-term mma.sync GEMM ----------------------------------
// g_h16[m][n] = fp16( dinv[m] * sum_k X[m][k] W[k][n] )
__global__ void __launch_bounds__(256) k_mgemm(const float* __restrict__ Xext,
                                               const float* __restrict__ W,
                                               int srcSel) {
    __shared__ uint32_t sHi[16 * 128];   // 8 KB
    __shared__ uint32_t sLo[16 * 128];   // 8 KB

    const float* X = srcSel ? g_buf1 : Xext;
    __half2*     H = g_h16;

    int tid = threadIdx.x, wid = tid >> 5, lane = tid & 31;
    int nbase = wid * 16;

    // ---- W fragments (hi+lo) in registers, once per CTA ----
    uint32_t Whi[8][2][2], Wlo[8][2][2];
    #pragma unroll
    for (int ks = 0; ks < 8; ks++) {
        #pragma unroll
        for (int nb = 0; nb < 2; nb++) {
            int col = nbase + nb * 8 + (lane >> 2);
            int k0  = ks * 16 + (lane & 3) * 2;
            float w00 = W[(k0 + 0) * 128 + col];
            float w01 = W[(k0 + 1) * 128 + col];
            float w10 = W[(k0 + 8) * 128 + col];
            float w11 = W[(k0 + 9) * 128 + col];
            float h00 = bf16_round(w00), h01 = bf16_round(w01);
            float h10 = bf16_round(w10), h11 = bf16_round(w11);
            Whi[ks][nb][0] = pack_bf16(h00, h01);
            Whi[ks][nb][1] = pack_bf16(h10, h11);
            Wlo[ks][nb][0] = pack_bf16(w00 - h00, w01 - h01);
            Wlo[ks][nb][1] = pack_bf16(w10 - h10, w11 - h11);
        }
    }

    int rowBase = blockIdx.x * 128;
    const float4* Xv = (const float4*)X;

    float4 pv[4];
    #pragma unroll
    for (int i = 0; i < 4; i++) {
        int lin = tid + 256 * i;
        int rl = lin >> 5, kq = lin & 31;
        int gr = rowBase + rl;
        pv[i] = (gr < N_NODES) ? Xv[(size_t)gr * 32 + kq]
                               : make_float4(0.f, 0.f, 0.f, 0.f);
    }

    #pragma unroll 1
    for (int slab = 0; slab < 4; slab++) {
        __syncthreads();

        #pragma unroll
        for (int i = 0; i < 4; i++) {
            int lin = tid + 256 * i;
            int rl = lin >> 5, kq = lin & 31;
            int mb = rl >> 4, rloc = rl & 15;
            int ks = kq >> 2;
            int j = ((rloc >> 3) & 1) + (((kq >> 1) & 1) << 1);
            int slot = (rloc & 7) * 4 + 2 * (kq & 1);
            int slot_sw = slot ^ (ks << 2);
            int base = (mb * 8 + ks) * 128 + slot_sw * 4 + j;
            float4 v = pv[i];
            float hx = bf16_round(v.x), hy = bf16_round(v.y);
            float hz = bf16_round(v.z), hw = bf16_round(v.w);
            sHi[base]     = pack_bf16(hx, hy);
            sHi[base + 4] = pack_bf16(hz, hw);
            sLo[base]     = pack_bf16(v.x - hx, v.y - hy);
            sLo[base + 4] = pack_bf16(v.z - hz, v.w - hw);
        }
        __syncthreads();

        if (slab < 3) {
            #pragma unroll
            for (int i = 0; i < 4; i++) {
                int lin = tid + 256 * i;
                int rl = lin >> 5, kq = lin & 31;
                int gr = rowBase + (slab + 1) * 32 + rl;
                pv[i] = (gr < N_NODES) ? Xv[(size_t)gr * 32 + kq]
                                       : make_float4(0.f, 0.f, 0.f, 0.f);
            }
        }

        #pragma unroll 1
        for (int mb = 0; mb < 2; mb++) {
            float a0[2][4], a1[2][4], a2[2][4];
            #pragma unroll
            for (int nb = 0; nb < 2; nb++)
                #pragma unroll
                for (int j = 0; j < 4; j++) { a0[nb][j] = 0.f; a1[nb][j] = 0.f; a2[nb][j] = 0.f; }

            #pragma unroll
            for (int ks = 0; ks < 8; ks++) {
                int idx = (mb * 8 + ks) * 128 + (lane ^ (ks << 2)) * 4;
                uint4 ah = *(const uint4*)&sHi[idx];
                uint4 al = *(const uint4*)&sLo[idx];
                #pragma unroll
                for (int nb = 0; nb < 2; nb++) {
                    mma_bf16(a0[nb], ah.x, ah.y, ah.z, ah.w,
                             Whi[ks][nb][0], Whi[ks][nb][1]);
                    mma_bf16(a1[nb], al.x, al.y, al.z, al.w,
                             Whi[ks][nb][0], Whi[ks][nb][1]);
                    mma_bf16(a2[nb], ah.x, ah.y, ah.z, ah.w,
                             Wlo[ks][nb][0], Wlo[ks][nb][1]);
                }
            }

            int r0 = rowBase + slab * 32 + mb * 16 + (lane >> 2);
            int r1 = r0 + 8;
            float d0 = (r0 < N_NODES) ? g_dinv[r0] : 0.f;
            float d1 = (r1 < N_NODES) ? g_dinv[r1] : 0.f;
            #pragma unroll
            for (int nb = 0; nb < 2; nb++) {
                int cc = nbase + nb * 8 + (lane & 3) * 2;
                float s0 = a0[nb][0] + a1[nb][0] + a2[nb][0];
                float s1 = a0[nb][1] + a1[nb][1] + a2[nb][1];
                float s2 = a0[nb][2] + a1[nb][2] + a2[nb][2];
                float s3 = a0[nb][3] + a1[nb][3] + a2[nb][3];
                if (r0 < N_NODES)
                    H[(size_t)r0 * 64 + (cc >> 1)] = __floats2half2_rn(s0 * d0, s1 * d0);
                if (r1 < N_NODES)
                    H[(size_t)r1 * 64 + (cc >> 1)] = __floats2half2_rn(s2 * d1, s3 * d1);
            }
        }
    }
}

// ---------------- aggregation: fp16 gather, fp32 accumulate ------------------
// out[c] = dinv[c]*(xts16[c] + sum_in xts16[s]) + bias
__global__ void __launch_bounds__(256) k_agg(const float* __restrict__ bias,
                                             float* __restrict__ outExt,
                                             int useExtOut) {
    int gw = (blockIdx.x * blockDim.x + threadIdx.x) >> 5;
    int lane = threadIdx.x & 31;
    if (gw >= N_NODES) return;
    int c = gw;

    const uint2* hv = (const uint2*)g_h16;    // 32 uint2 per row (4 halves each)
    float*       out = useExtOut ? outExt : g_buf1;

    float4 acc = unpack4(hv[(size_t)c * 32 + lane]);   // self term

    int e0 = g_off[c], e1 = g_off[c + 1];
    int e = e0;
    for (; e + 4 <= e1; e += 4) {
        int s0 = __ldg(&g_src[e]);
        int s1 = __ldg(&g_src[e + 1]);
        int s2 = __ldg(&g_src[e + 2]);
        int s3 = __ldg(&g_src[e + 3]);
        uint2 u0 = hv[(size_t)s0 * 32 + lane];
        uint2 u1 = hv[(size_t)s1 * 32 + lane];
        uint2 u2 = hv[(size_t)s2 * 32 + lane];
        uint2 u3 = hv[(size_t)s3 * 32 + lane];
        float4 v0 = unpack4(u0), v1 = unpack4(u1);
        float4 v2 = unpack4(u2), v3 = unpack4(u3);
        acc.x += v0.x + v1.x + v2.x + v3.x;
        acc.y += v0.y + v1.y + v2.y + v3.y;
        acc.z += v0.z + v1.z + v2.z + v3.z;
        acc.w += v0.w + v1.w + v2.w + v3.w;
    }
    for (; e < e1; e++) {
        int s = __ldg(&g_src[e]);
        float4 v = unpack4(hv[(size_t)s * 32 + lane]);
        acc.x += v.x; acc.y += v.y; acc.z += v.z; acc.w += v.w;
    }

    float dc = g_dinv[c];
    float4 b = ((const float4*)bias)[lane];
    acc.x = acc.x * dc + b.x; acc.y = acc.y * dc + b.y;
    acc.z = acc.z * dc + b.z; acc.w = acc.w * dc + b.w;
    ((float4*)out)[(size_t)c * 32 + lane] = acc;
}

// ---------------- launch -----------------------------------------------------
extern "C" void kernel_launch(void* const* d_in, const int* in_sizes, int n_in,
                              void* d_out, int out_size) {
    const float* X  = (const float*)d_in[0];
    const void*  EI = d_in[1];
    const float* W1 = (const float*)d_in[2];
    const float* B1 = (const float*)d_in[3];
    const float* W2 = (const float*)d_in[4];
    const float* B2 = (const float*)d_in[5];
    float*       out = (float*)d_out;

    const int edgeBlocks = (N_EDGES + 255) / 256;
    const int aggBlocks  = (N_NODES * 32 + 255) / 256;

    // build CSC (by destination) + dinv
    k_init<<<NBLK, 256>>>((const int*)EI);
    k_count<<<edgeBlocks, 256>>>(EI);
    k_blocksum<<<NBLK, 256>>>();
    k_scanb<<<1, 512>>>();
    k_offsets<<<NBLK, 256>>>();
    k_fill<<<edgeBlocks, 256>>>(EI);

    // layer 1
    k_mgemm<<<N_TILES, 256>>>(X, W1, /*src=*/0);         // xts16 -> g_h16
    k_agg<<<aggBlocks, 256>>>(B1, out, /*useExtOut=*/0); // h -> buf1 (fp32)

    // layer 2
    k_mgemm<<<N_TILES, 256>>>(nullptr, W2, /*src=*/1);   // xts16 -> g_h16
    k_agg<<<aggBlocks, 256>>>(B2, out, /*useExtOut=*/1); // -> d_out
}

// round 10
// speedup vs baseline: 1.8085x; 1.0199x over previous
#include <cuda_runtime.h>
#include <cuda_bf16.h>
#include <cuda_fp16.h>
#include <cstdint>

#define N_NODES 100000
#define N_EDGES 1600000
#define HID 128
#define NBLK ((N_NODES + 255) / 256)     // 391
#define N_TILES ((N_NODES + 127) / 128)  // 782

// ---------------- scratch ----------------------------------------------------
__device__ __align__(16) __half2 g_h16[(size_t)N_NODES * 64]; // xts in fp16
__device__ __align__(16) float g_buf1[(size_t)N_NODES * HID]; // layer-1 hidden (fp32)
__device__ float g_dinv[N_NODES];
__device__ int   g_deg[N_NODES];
__device__ int   g_cur[N_NODES];
__device__ int   g_off[N_NODES];
__device__ int   g_src[N_EDGES];
__device__ int   g_total;
__device__ int   g_is64;

// ---------------- helpers ----------------------------------------------------
__device__ __forceinline__ uint32_t pack_bf16(float lo, float hi) {
    uint32_t r;
    asm("cvt.rn.bf16x2.f32 %0, %1, %2;" : "=r"(r) : "f"(hi), "f"(lo));
    return r;
}
__device__ __forceinline__ float bf16_round(float v) {
    __nv_bfloat16 h = __float2bfloat16_rn(v);
    return __bfloat162float(h);
}

__device__ __forceinline__ void mma_bf16(float c[4], uint32_t a0, uint32_t a1,
                                         uint32_t a2, uint32_t a3,
                                         uint32_t b0, uint32_t b1) {
    asm("mma.sync.aligned.m16n8k16.row.col.f32.bf16.bf16.f32 "
        "{%0,%1,%2,%3},{%4,%5,%6,%7},{%8,%9},{%0,%1,%2,%3};"
        : "+f"(c[0]), "+f"(c[1]), "+f"(c[2]), "+f"(c[3])
        : "r"(a0), "r"(a1), "r"(a2), "r"(a3), "r"(b0), "r"(b1));
}

// accumulate 8 halves (one uint4) into 8 fp32 accumulators
__device__ __forceinline__ void acc8(float* acc, uint4 u) {
    float2 f;
    f = __half22float2(*(__half2*)&u.x); acc[0] += f.x; acc[1] += f.y;
    f = __half22float2(*(__half2*)&u.y); acc[2] += f.x; acc[3] += f.y;
    f = __half22float2(*(__half2*)&u.z); acc[4] += f.x; acc[5] += f.y;
    f = __half22float2(*(__half2*)&u.w); acc[6] += f.x; acc[7] += f.y;
}

// ---------------- init: zero counters + dtype probe (block 0) ----------------
__global__ void k_init(const int* __restrict__ ei32) {
    int i = blockIdx.x * 256 + threadIdx.x;
    if (i < N_NODES) { g_deg[i] = 0; g_cur[i] = 0; }
    if (i == 0) g_total = 0;
    if (blockIdx.x == 0) {
        __shared__ int anyNZ;
        if (threadIdx.x == 0) anyNZ = 0;
        __syncthreads();
        int nz = 0;
        #pragma unroll
        for (int j = 0; j < 8; j++) {
            int idx = 2 * (threadIdx.x + 256 * j) + 1;   // odd words
            if (ei32[idx] != 0) nz = 1;
        }
        if (nz) atomicOr(&anyNZ, 1);
        __syncthreads();
        if (threadIdx.x == 0) g_is64 = anyNZ ? 0 : 1;
    }
}

__device__ __forceinline__ int edge_at(const void* ei, long long idx) {
    if (g_is64) return (int)((const long long*)ei)[idx];
    return ((const int*)ei)[idx];
}

// ---------------- graph build ------------------------------------------------
__global__ void k_count(const void* __restrict__ ei) {
    int e = blockIdx.x * blockDim.x + threadIdx.x;
    if (e < N_EDGES) {
        int c = edge_at(ei, (long long)N_EDGES + e);
        if ((unsigned)c < N_NODES) atomicAdd(&g_deg[c], 1);
    }
}

// fused per-block scan + atomic block base + dinv (one kernel)
__global__ void k_offa() {
    __shared__ int sh[256];
    __shared__ int base;
    int t = threadIdx.x;
    int i = blockIdx.x * 256 + t;
    int d = (i < N_NODES) ? g_deg[i] : 0;
    sh[t] = d;
    __syncthreads();
    #pragma unroll
    for (int off = 1; off < 256; off <<= 1) {
        int u = (t >= off) ? sh[t - off] : 0;
        __syncthreads();
        sh[t] += u;
        __syncthreads();
    }
    if (t == 255) base = atomicAdd(&g_total, sh[255]);
    __syncthreads();
    if (i < N_NODES) {
        g_off[i] = base + sh[t] - d;
        g_dinv[i] = rsqrtf((float)(d + 1));
    }
}

__global__ void k_fill(const void* __restrict__ ei) {
    int e = blockIdx.x * blockDim.x + threadIdx.x;
    if (e < N_EDGES) {
        int r = edge_at(ei, e);
        int c = edge_at(ei, (long long)N_EDGES + e);
        if ((unsigned)r >= N_NODES || (unsigned)c >= N_NODES) return;
        int pos = g_off[c] + atomicAdd(&g_cur[c], 1);
        if ((unsigned)pos < N_EDGES) g_src[pos] = r;
    }
}

// ---------------- bf16 3-term mma.sync GEMM ----------------------------------
// g_h16[m][n] = fp16( dinv[m] * sum_k X[m][k] W[k][n] )
__global__ void __launch_bounds__(256, 2) k_mgemm(const float* __restrict__ Xext,
                                                  const float* __restrict__ W,
                                                  int srcSel) {
    __shared__ uint32_t sHi[16 * 128];   // 8 KB
    __shared__ uint32_t sLo[16 * 128];   // 8 KB

    const float* X = srcSel ? g_buf1 : Xext;
    __half2*     H = g_h16;

    int tid = threadIdx.x, wid = tid >> 5, lane = tid & 31;
    int nbase = wid * 16;

    // ---- W fragments (hi+lo) in registers, once per CTA ----
    uint32_t Whi[8][2][2], Wlo[8][2][2];
    #pragma unroll
    for (int ks = 0; ks < 8; ks++) {
        #pragma unroll
        for (int nb = 0; nb < 2; nb++) {
            int col = nbase + nb * 8 + (lane >> 2);
            int k0  = ks * 16 + (lane & 3) * 2;
            float w00 = W[(k0 + 0) * 128 + col];
            float w01 = W[(k0 + 1) * 128 + col];
            float w10 = W[(k0 + 8) * 128 + col];
            float w11 = W[(k0 + 9) * 128 + col];
            float h00 = bf16_round(w00), h01 = bf16_round(w01);
            float h10 = bf16_round(w10), h11 = bf16_round(w11);
            Whi[ks][nb][0] = pack_bf16(h00, h01);
            Whi[ks][nb][1] = pack_bf16(h10, h11);
            Wlo[ks][nb][0] = pack_bf16(w00 - h00, w01 - h01);
            Wlo[ks][nb][1] = pack_bf16(w10 - h10, w11 - h11);
        }
    }

    int rowBase = blockIdx.x * 128;
    const float4* Xv = (const float4*)X;

    float4 pv[4];
    #pragma unroll
    for (int i = 0; i < 4; i++) {
        int lin = tid + 256 * i;
        int rl = lin >> 5, kq = lin & 31;
        int gr = rowBase + rl;
        pv[i] = (gr < N_NODES) ? Xv[(size_t)gr * 32 + kq]
                               : make_float4(0.f, 0.f, 0.f, 0.f);
    }

    #pragma unroll 1
    for (int slab = 0; slab < 4; slab++) {
        __syncthreads();

        #pragma unroll
        for (int i = 0; i < 4; i++) {
            int lin = tid + 256 * i;
            int rl = lin >> 5, kq = lin & 31;
            int mb = rl >> 4, rloc = rl & 15;
            int ks = kq >> 2;
            int j = ((rloc >> 3) & 1) + (((kq >> 1) & 1) << 1);
            int slot = (rloc & 7) * 4 + 2 * (kq & 1);
            int slot_sw = slot ^ (ks << 2);
            int base = (mb * 8 + ks) * 128 + slot_sw * 4 + j;
            float4 v = pv[i];
            float hx = bf16_round(v.x), hy = bf16_round(v.y);
            float hz = bf16_round(v.z), hw = bf16_round(v.w);
            sHi[base]     = pack_bf16(hx, hy);
            sHi[base + 4] = pack_bf16(hz, hw);
            sLo[base]     = pack_bf16(v.x - hx, v.y - hy);
            sLo[base + 4] = pack_bf16(v.z - hz, v.w - hw);
        }
        __syncthreads();

        if (slab < 3) {
            #pragma unroll
            for (int i = 0; i < 4; i++) {
                int lin = tid + 256 * i;
                int rl = lin >> 5, kq = lin & 31;
                int gr = rowBase + (slab + 1) * 32 + rl;
                pv[i] = (gr < N_NODES) ? Xv[(size_t)gr * 32 + kq]
                                       : make_float4(0.f, 0.f, 0.f, 0.f);
            }
        }

        #pragma unroll 1
        for (int mb = 0; mb < 2; mb++) {
            float a0[2][4], a1[2][4], a2[2][4];
            #pragma unroll
            for (int nb = 0; nb < 2; nb++)
                #pragma unroll
                for (int j = 0; j < 4; j++) { a0[nb][j] = 0.f; a1[nb][j] = 0.f; a2[nb][j] = 0.f; }

            #pragma unroll
            for (int ks = 0; ks < 8; ks++) {
                int idx = (mb * 8 + ks) * 128 + (lane ^ (ks << 2)) * 4;
                uint4 ah = *(const uint4*)&sHi[idx];
                uint4 al = *(const uint4*)&sLo[idx];
                #pragma unroll
                for (int nb = 0; nb < 2; nb++) {
                    mma_bf16(a0[nb], ah.x, ah.y, ah.z, ah.w,
                             Whi[ks][nb][0], Whi[ks][nb][1]);
                    mma_bf16(a1[nb], al.x, al.y, al.z, al.w,
                             Whi[ks][nb][0], Whi[ks][nb][1]);
                    mma_bf16(a2[nb], ah.x, ah.y, ah.z, ah.w,
                             Wlo[ks][nb][0], Wlo[ks][nb][1]);
                }
            }

            int r0 = rowBase + slab * 32 + mb * 16 + (lane >> 2);
            int r1 = r0 + 8;
            float d0 = (r0 < N_NODES) ? g_dinv[r0] : 0.f;
            float d1 = (r1 < N_NODES) ? g_dinv[r1] : 0.f;
            #pragma unroll
            for (int nb = 0; nb < 2; nb++) {
                int cc = nbase + nb * 8 + (lane & 3) * 2;
                float s0 = a0[nb][0] + a1[nb][0] + a2[nb][0];
                float s1 = a0[nb][1] + a1[nb][1] + a2[nb][1];
                float s2 = a0[nb][2] + a1[nb][2] + a2[nb][2];
                float s3 = a0[nb][3] + a1[nb][3] + a2[nb][3];
                if (r0 < N_NODES)
                    H[(size_t)r0 * 64 + (cc >> 1)] = __floats2half2_rn(s0 * d0, s1 * d0);
                if (r1 < N_NODES)
                    H[(size_t)r1 * 64 + (cc >> 1)] = __floats2half2_rn(s2 * d1, s3 * d1);
            }
        }
    }
}

// ---------------- aggregation: 2 edges per LDG.128, shfl combine -------------
// out[c] = dinv[c]*(xts16[c] + sum_in xts16[s]) + bias
// half-warp 0 (lanes 0-15) accumulates even edges, half-warp 1 odd edges;
// each lane owns 8 features (ln*8..ln*8+7); combine via shfl_xor(16).
__global__ void __launch_bounds__(256) k_agg(const float* __restrict__ bias,
                                             float* __restrict__ outExt,
                                             int useExtOut) {
    int gw = (blockIdx.x * blockDim.x + threadIdx.x) >> 5;
    int lane = threadIdx.x & 31;
    if (gw >= N_NODES) return;
    int c = gw;
    int sub = lane >> 4;        // 0: even edges, 1: odd edges
    int ln  = lane & 15;        // feature-slice owner (8 floats)

    const uint4* hv4 = (const uint4*)g_h16;   // 16 uint4 per row
    float*       out = useExtOut ? outExt : g_buf1;

    float acc[8];
    #pragma unroll
    for (int j = 0; j < 8; j++) acc[j] = 0.f;

    // self term on even half
    if (sub == 0) acc8(acc, hv4[(size_t)c * 16 + ln]);

    int e0 = g_off[c];
    int e1 = e0 + g_deg[c];
    int e = e0;

    // 8 edges (4 pairs) per iteration
    for (; e + 8 <= e1; e += 8) {
        int s0 = __ldg(&g_src[e     + sub]);
        int s1 = __ldg(&g_src[e + 2 + sub]);
        int s2 = __ldg(&g_src[e + 4 + sub]);
        int s3 = __ldg(&g_src[e + 6 + sub]);
        uint4 u0 = hv4[(size_t)s0 * 16 + ln];
        uint4 u1 = hv4[(size_t)s1 * 16 + ln];
        uint4 u2 = hv4[(size_t)s2 * 16 + ln];
        uint4 u3 = hv4[(size_t)s3 * 16 + ln];
        acc8(acc, u0); acc8(acc, u1); acc8(acc, u2); acc8(acc, u3);
    }
    // pair tail
    for (; e < e1; e += 2) {
        int idx = e + sub;
        if (idx < e1) {
            int s = __ldg(&g_src[idx]);
            acc8(acc, hv4[(size_t)s * 16 + ln]);
        }
    }

    // combine halves
    float res[8];
    #pragma unroll
    for (int j = 0; j < 8; j++)
        res[j] = acc[j] + __shfl_xor_sync(0xFFFFFFFFu, acc[j], 16);

    float dc = g_dinv[c];
    int o0 = sub * 4;                       // which half of the 8-feature slice
    int fslot = ln * 2 + sub;               // float4 slot 0..31
    float4 b = ((const float4*)bias)[fslot];
    float4 o = make_float4(res[o0 + 0] * dc + b.x, res[o0 + 1] * dc + b.y,
                           res[o0 + 2] * dc + b.z, res[o0 + 3] * dc + b.w);
    ((float4*)out)[(size_t)c * 32 + fslot] = o;
}

// ---------------- launch -----------------------------------------------------
extern "C" void kernel_launch(void* const* d_in, const int* in_sizes, int n_in,
                              void* d_out, int out_size) {
    const float* X  = (const float*)d_in[0];
    const void*  EI = d_in[1];
    const float* W1 = (const float*)d_in[2];
    const float* B1 = (const float*)d_in[3];
    const float* W2 = (const float*)d_in[4];
    const float* B2 = (const float*)d_in[5];
    float*       out = (float*)d_out;

    const int edgeBlocks = (N_EDGES + 255) / 256;
    const int aggBlocks  = (N_NODES * 32 + 255) / 256;

    k_init<<<NBLK, 256>>>((const int*)EI);            // 0
    k_count<<<edgeBlocks, 256>>>(EI);                 // 1
    k_offa<<<NBLK, 256>>>();                          // 2 (needs count)
    k_mgemm<<<N_TILES, 256>>>(X, W1, /*src=*/0);      // 3 <- profiled launch
    k_fill<<<edgeBlocks, 256>>>(EI);                  // 4 (needs offa)
    k_agg<<<aggBlocks, 256>>>(B1, out, 0);            // 5: h -> buf1
    k_mgemm<<<N_TILES, 256>>>(nullptr, W2, /*src=*/1);// 6
    k_agg<<<aggBlocks, 256>>>(B2, out, 1);            // 7: -> d_out
}

// round 11
// speedup vs baseline: 1.8248x; 1.0090x over previous
#include <cuda_runtime.h>
#include <cuda_bf16.h>
#include <cuda_fp16.h>
#include <cstdint>

#define N_NODES 100000
#define N_EDGES 1600000
#define HID 128
#define NBLK ((N_NODES + 255) / 256)     // 391
#define N_TILES ((N_NODES + 127) / 128)  // 782

// ---------------- scratch ----------------------------------------------------
__device__ __align__(16) __half2 g_h16[(size_t)N_NODES * 64]; // xts in fp16
__device__ __align__(16) float g_buf1[(size_t)N_NODES * HID]; // layer-1 hidden (fp32)
__device__ float g_dinv[N_NODES];
__device__ int   g_deg[N_NODES];
__device__ int   g_cur[N_NODES];
__device__ int   g_off[N_NODES];
__device__ int   g_src[N_EDGES];
__device__ int   g_total;
__device__ int   g_is64;

// ---------------- helpers ----------------------------------------------------
__device__ __forceinline__ uint32_t pack_bf16(float lo, float hi) {
    uint32_t r;
    asm("cvt.rn.bf16x2.f32 %0, %1, %2;" : "=r"(r) : "f"(hi), "f"(lo));
    return r;
}
__device__ __forceinline__ float bf16_round(float v) {
    __nv_bfloat16 h = __float2bfloat16_rn(v);
    return __bfloat162float(h);
}

__device__ __forceinline__ void mma_bf16(float c[4], uint32_t a0, uint32_t a1,
                                         uint32_t a2, uint32_t a3,
                                         uint32_t b0, uint32_t b1) {
    asm("mma.sync.aligned.m16n8k16.row.col.f32.bf16.bf16.f32 "
        "{%0,%1,%2,%3},{%4,%5,%6,%7},{%8,%9},{%0,%1,%2,%3};"
        : "+f"(c[0]), "+f"(c[1]), "+f"(c[2]), "+f"(c[3])
        : "r"(a0), "r"(a1), "r"(a2), "r"(a3), "r"(b0), "r"(b1));
}

// accumulate 8 halves (one uint4) into 8 fp32 accumulators
__device__ __forceinline__ void acc8(float* acc, uint4 u) {
    float2 f;
    f = __half22float2(*(__half2*)&u.x); acc[0] += f.x; acc[1] += f.y;
    f = __half22float2(*(__half2*)&u.y); acc[2] += f.x; acc[3] += f.y;
    f = __half22float2(*(__half2*)&u.z); acc[4] += f.x; acc[5] += f.y;
    f = __half22float2(*(__half2*)&u.w); acc[6] += f.x; acc[7] += f.y;
}

// ---------------- init: zero counters + dtype probe (block 0) ----------------
__global__ void k_init(const int* __restrict__ ei32) {
    int i = blockIdx.x * 256 + threadIdx.x;
    if (i < N_NODES) { g_deg[i] = 0; g_cur[i] = 0; }
    if (i == 0) g_total = 0;
    if (blockIdx.x == 0) {
        __shared__ int anyNZ;
        if (threadIdx.x == 0) anyNZ = 0;
        __syncthreads();
        int nz = 0;
        #pragma unroll
        for (int j = 0; j < 8; j++) {
            int idx = 2 * (threadIdx.x + 256 * j) + 1;   // odd words
            if (ei32[idx] != 0) nz = 1;
        }
        if (nz) atomicOr(&anyNZ, 1);
        __syncthreads();
        if (threadIdx.x == 0) g_is64 = anyNZ ? 0 : 1;
    }
}

__device__ __forceinline__ int edge_at(const void* ei, long long idx) {
    if (g_is64) return (int)((const long long*)ei)[idx];
    return ((const int*)ei)[idx];
}

// ---------------- graph build ------------------------------------------------
__global__ void k_count(const void* __restrict__ ei) {
    int e = blockIdx.x * blockDim.x + threadIdx.x;
    if (e < N_EDGES) {
        int c = edge_at(ei, (long long)N_EDGES + e);
        if ((unsigned)c < N_NODES) atomicAdd(&g_deg[c], 1);
    }
}

// fused per-block scan + atomic block base + dinv
__global__ void k_offa() {
    __shared__ int sh[256];
    __shared__ int base;
    int t = threadIdx.x;
    int i = blockIdx.x * 256 + t;
    int d = (i < N_NODES) ? g_deg[i] : 0;
    sh[t] = d;
    __syncthreads();
    #pragma unroll
    for (int off = 1; off < 256; off <<= 1) {
        int u = (t >= off) ? sh[t - off] : 0;
        __syncthreads();
        sh[t] += u;
        __syncthreads();
    }
    if (t == 255) base = atomicAdd(&g_total, sh[255]);
    __syncthreads();
    if (i < N_NODES) {
        g_off[i] = base + sh[t] - d;
        g_dinv[i] = rsqrtf((float)(d + 1));
    }
}

__global__ void k_fill(const void* __restrict__ ei) {
    int e = blockIdx.x * blockDim.x + threadIdx.x;
    if (e < N_EDGES) {
        int r = edge_at(ei, e);
        int c = edge_at(ei, (long long)N_EDGES + e);
        if ((unsigned)r >= N_NODES || (unsigned)c >= N_NODES) return;
        int pos = g_off[c] + atomicAdd(&g_cur[c], 1);
        if ((unsigned)pos < N_EDGES) g_src[pos] = r;
    }
}

// ---------------- bf16 3-term mma.sync GEMM, double-buffered -----------------
// g_h16[m][n] = fp16( dinv[m] * sum_k X[m][k] W[k][n] )
// Per slab: store(s)->buf[s&1]; sync; prefetch(s+1); compute(buf[s&1]).
// buf[s&1] is rewritten only at s+2, after sync(s+1) which every thread
// passes only after finishing compute(s) -> hazard-free with ONE sync/slab.
__global__ void __launch_bounds__(256, 2) k_mgemm(const float* __restrict__ Xext,
                                                  const float* __restrict__ W,
                                                  int srcSel) {
    __shared__ uint32_t sHi[2][16 * 128];   // 2 x 8 KB
    __shared__ uint32_t sLo[2][16 * 128];   // 2 x 8 KB

    const float* X = srcSel ? g_buf1 : Xext;
    __half2*     H = g_h16;

    int tid = threadIdx.x, wid = tid >> 5, lane = tid & 31;
    int nbase = wid * 16;

    // ---- W fragments (hi+lo) in registers, once per CTA ----
    uint32_t Whi[8][2][2], Wlo[8][2][2];
    #pragma unroll
    for (int ks = 0; ks < 8; ks++) {
        #pragma unroll
        for (int nb = 0; nb < 2; nb++) {
            int col = nbase + nb * 8 + (lane >> 2);
            int k0  = ks * 16 + (lane & 3) * 2;
            float w00 = W[(k0 + 0) * 128 + col];
            float w01 = W[(k0 + 1) * 128 + col];
            float w10 = W[(k0 + 8) * 128 + col];
            float w11 = W[(k0 + 9) * 128 + col];
            float h00 = bf16_round(w00), h01 = bf16_round(w01);
            float h10 = bf16_round(w10), h11 = bf16_round(w11);
            Whi[ks][nb][0] = pack_bf16(h00, h01);
            Whi[ks][nb][1] = pack_bf16(h10, h11);
            Wlo[ks][nb][0] = pack_bf16(w00 - h00, w01 - h01);
            Wlo[ks][nb][1] = pack_bf16(w10 - h10, w11 - h11);
        }
    }

    int rowBase = blockIdx.x * 128;
    const float4* Xv = (const float4*)X;

    // precomputed store-address pieces (loop-invariant)
    int sAddr[4];
    #pragma unroll
    for (int i = 0; i < 4; i++) {
        int lin = tid + 256 * i;
        int rl = lin >> 5, kq = lin & 31;
        int mb = rl >> 4, rloc = rl & 15;
        int ks = kq >> 2;
        int j = ((rloc >> 3) & 1) + (((kq >> 1) & 1) << 1);
        int slot = (rloc & 7) * 4 + 2 * (kq & 1);
        int slot_sw = slot ^ (ks << 2);
        sAddr[i] = (mb * 8 + ks) * 128 + slot_sw * 4 + j;
    }

    // prefetch slab 0
    float4 pv[4];
    #pragma unroll
    for (int i = 0; i < 4; i++) {
        int lin = tid + 256 * i;
        int rl = lin >> 5, kq = lin & 31;
        int gr = rowBase + rl;
        pv[i] = (gr < N_NODES) ? Xv[(size_t)gr * 32 + kq]
                               : make_float4(0.f, 0.f, 0.f, 0.f);
    }

    #pragma unroll 1
    for (int slab = 0; slab < 4; slab++) {
        int buf = slab & 1;

        // ---- store prefetched slab into buf ----
        #pragma unroll
        for (int i = 0; i < 4; i++) {
            int base = sAddr[i];
            float4 v = pv[i];
            float hx = bf16_round(v.x), hy = bf16_round(v.y);
            float hz = bf16_round(v.z), hw = bf16_round(v.w);
            sHi[buf][base]     = pack_bf16(hx, hy);
            sHi[buf][base + 4] = pack_bf16(hz, hw);
            sLo[buf][base]     = pack_bf16(v.x - hx, v.y - hy);
            sLo[buf][base + 4] = pack_bf16(v.z - hz, v.w - hw);
        }
        __syncthreads();                    // only sync per slab

        // ---- prefetch next slab (overlaps compute below) ----
        if (slab < 3) {
            #pragma unroll
            for (int i = 0; i < 4; i++) {
                int lin = tid + 256 * i;
                int rl = lin >> 5, kq = lin & 31;
                int gr = rowBase + (slab + 1) * 32 + rl;
                pv[i] = (gr < N_NODES) ? Xv[(size_t)gr * 32 + kq]
                                       : make_float4(0.f, 0.f, 0.f, 0.f);
            }
        }

        // ---- compute 2 m-blocks from buf ----
        #pragma unroll 1
        for (int mb = 0; mb < 2; mb++) {
            float a0[2][4], a1[2][4], a2[2][4];
            #pragma unroll
            for (int nb = 0; nb < 2; nb++)
                #pragma unroll
                for (int j = 0; j < 4; j++) { a0[nb][j] = 0.f; a1[nb][j] = 0.f; a2[nb][j] = 0.f; }

            #pragma unroll
            for (int ks = 0; ks < 8; ks++) {
                int idx = (mb * 8 + ks) * 128 + (lane ^ (ks << 2)) * 4;
                uint4 ah = *(const uint4*)&sHi[buf][idx];
                uint4 al = *(const uint4*)&sLo[buf][idx];
                #pragma unroll
                for (int nb = 0; nb < 2; nb++) {
                    mma_bf16(a0[nb], ah.x, ah.y, ah.z, ah.w,
                             Whi[ks][nb][0], Whi[ks][nb][1]);
                    mma_bf16(a1[nb], al.x, al.y, al.z, al.w,
                             Whi[ks][nb][0], Whi[ks][nb][1]);
                    mma_bf16(a2[nb], ah.x, ah.y, ah.z, ah.w,
                             Wlo[ks][nb][0], Wlo[ks][nb][1]);
                }
            }

            int r0 = rowBase + slab * 32 + mb * 16 + (lane >> 2);
            int r1 = r0 + 8;
            float d0 = (r0 < N_NODES) ? g_dinv[r0] : 0.f;
            float d1 = (r1 < N_NODES) ? g_dinv[r1] : 0.f;
            #pragma unroll
            for (int nb = 0; nb < 2; nb++) {
                int cc = nbase + nb * 8 + (lane & 3) * 2;
                float s0 = a0[nb][0] + a1[nb][0] + a2[nb][0];
                float s1 = a0[nb][1] + a1[nb][1] + a2[nb][1];
                float s2 = a0[nb][2] + a1[nb][2] + a2[nb][2];
                float s3 = a0[nb][3] + a1[nb][3] + a2[nb][3];
                if (r0 < N_NODES)
                    H[(size_t)r0 * 64 + (cc >> 1)] = __floats2half2_rn(s0 * d0, s1 * d0);
                if (r1 < N_NODES)
                    H[(size_t)r1 * 64 + (cc >> 1)] = __floats2half2_rn(s2 * d1, s3 * d1);
            }
        }
        // no trailing sync: next store targets the other buffer
    }
}

// ---------------- aggregation: 2 edges per LDG.128, shfl combine -------------
// out[c] = dinv[c]*(xts16[c] + sum_in xts16[s]) + bias
__global__ void __launch_bounds__(256) k_agg(const float* __restrict__ bias,
                                             float* __restrict__ outExt,
                                             int useExtOut) {
    int gw = (blockIdx.x * blockDim.x + threadIdx.x) >> 5;
    int lane = threadIdx.x & 31;
    if (gw >= N_NODES) return;
    int c = gw;
    int sub = lane >> 4;        // 0: even edges, 1: odd edges
    int ln  = lane & 15;        // feature-slice owner (8 floats)

    const uint4* hv4 = (const uint4*)g_h16;   // 16 uint4 per row
    float*       out = useExtOut ? outExt : g_buf1;

    float acc[8];
    #pragma unroll
    for (int j = 0; j < 8; j++) acc[j] = 0.f;

    if (sub == 0) acc8(acc, hv4[(size_t)c * 16 + ln]);   // self term

    int e0 = g_off[c];
    int e1 = e0 + g_deg[c];
    int e = e0;

    for (; e + 8 <= e1; e += 8) {
        int s0 = __ldg(&g_src[e     + sub]);
        int s1 = __ldg(&g_src[e + 2 + sub]);
        int s2 = __ldg(&g_src[e + 4 + sub]);
        int s3 = __ldg(&g_src[e + 6 + sub]);
        uint4 u0 = hv4[(size_t)s0 * 16 + ln];
        uint4 u1 = hv4[(size_t)s1 * 16 + ln];
        uint4 u2 = hv4[(size_t)s2 * 16 + ln];
        uint4 u3 = hv4[(size_t)s3 * 16 + ln];
        acc8(acc, u0); acc8(acc, u1); acc8(acc, u2); acc8(acc, u3);
    }
    for (; e < e1; e += 2) {
        int idx = e + sub;
        if (idx < e1) {
            int s = __ldg(&g_src[idx]);
            acc8(acc, hv4[(size_t)s * 16 + ln]);
        }
    }

    float res[8];
    #pragma unroll
    for (int j = 0; j < 8; j++)
        res[j] = acc[j] + __shfl_xor_sync(0xFFFFFFFFu, acc[j], 16);

    float dc = g_dinv[c];
    int o0 = sub * 4;
    int fslot = ln * 2 + sub;
    float4 b = ((const float4*)bias)[fslot];
    float4 o = make_float4(res[o0 + 0] * dc + b.x, res[o0 + 1] * dc + b.y,
                           res[o0 + 2] * dc + b.z, res[o0 + 3] * dc + b.w);
    ((float4*)out)[(size_t)c * 32 + fslot] = o;
}

// ---------------- launch -----------------------------------------------------
extern "C" void kernel_launch(void* const* d_in, const int* in_sizes, int n_in,
                              void* d_out, int out_size) {
    const float* X  = (const float*)d_in[0];
    const void*  EI = d_in[1];
    const float* W1 = (const float*)d_in[2];
    const float* B1 = (const float*)d_in[3];
    const float* W2 = (const float*)d_in[4];
    const float* B2 = (const float*)d_in[5];
    float*       out = (float*)d_out;

    const int edgeBlocks = (N_EDGES + 255) / 256;
    const int aggBlocks  = (N_NODES * 32 + 255) / 256;

    k_init<<<NBLK, 256>>>((const int*)EI);            // 0
    k_count<<<edgeBlocks, 256>>>(EI);                 // 1
    k_offa<<<NBLK, 256>>>();                          // 2
    k_mgemm<<<N_TILES, 256>>>(X, W1, /*src=*/0);      // 3 <- profiled launch
    k_fill<<<edgeBlocks, 256>>>(EI);                  // 4
    k_agg<<<aggBlocks, 256>>>(B1, out, 0);            // 5: h -> buf1
    k_mgemm<<<N_TILES, 256>>>(nullptr, W2, /*src=*/1);// 6
    k_agg<<<aggBlocks, 256>>>(B2, out, 1);            // 7: -> d_out
}

// round 12
// speedup vs baseline: 1.9070x; 1.0451x over previous
#include <cuda_runtime.h>
#include <cuda_bf16.h>
#include <cuda_fp16.h>
#include <cstdint>

#define N_NODES 100000
#define N_EDGES 1600000
#define HID 128
#define NBLK ((N_NODES + 255) / 256)     // 391
#define N_TILES ((N_NODES + 127) / 128)  // 782

// ---------------- scratch ----------------------------------------------------
__device__ __align__(16) __half2 g_h16[(size_t)N_NODES * 64]; // xts in fp16
__device__ __align__(16) float g_buf1[(size_t)N_NODES * HID]; // layer-1 hidden (fp32)
__device__ float g_dinv[N_NODES];
__device__ int   g_deg[N_NODES];
__device__ int   g_cur[N_NODES];
__device__ int   g_off[N_NODES];
__device__ int   g_src[N_EDGES];
__device__ int   g_total;
__device__ int   g_is64;

// ---------------- helpers ----------------------------------------------------
__device__ __forceinline__ uint32_t smem_u32(const void* p) {
    uint32_t a;
    asm("{ .reg .u64 t; cvta.to.shared.u64 t, %1; cvt.u32.u64 %0, t; }"
        : "=r"(a) : "l"(p));
    return a;
}
__device__ __forceinline__ void cp_async16(uint32_t dst, const void* src, int srcBytes) {
    asm volatile("cp.async.cg.shared.global [%0], [%1], 16, %2;"
                 :: "r"(dst), "l"(src), "r"(srcBytes) : "memory");
}
#define CP_COMMIT() asm volatile("cp.async.commit_group;" ::: "memory")
template <int N>
__device__ __forceinline__ void cp_wait() {
    asm volatile("cp.async.wait_group %0;" :: "n"(N) : "memory");
}

__device__ __forceinline__ uint32_t pack_bf16(float lo, float hi) {
    uint32_t r;
    asm("cvt.rn.bf16x2.f32 %0, %1, %2;" : "=r"(r) : "f"(hi), "f"(lo));
    return r;
}
__device__ __forceinline__ float bf16_round(float v) {
    __nv_bfloat16 h = __float2bfloat16_rn(v);
    return __bfloat162float(h);
}

__device__ __forceinline__ void mma_bf16(float c[4], uint32_t a0, uint32_t a1,
                                         uint32_t a2, uint32_t a3,
                                         uint32_t b0, uint32_t b1) {
    asm("mma.sync.aligned.m16n8k16.row.col.f32.bf16.bf16.f32 "
        "{%0,%1,%2,%3},{%4,%5,%6,%7},{%8,%9},{%0,%1,%2,%3};"
        : "+f"(c[0]), "+f"(c[1]), "+f"(c[2]), "+f"(c[3])
        : "r"(a0), "r"(a1), "r"(a2), "r"(a3), "r"(b0), "r"(b1));
}

// accumulate 8 halves (one uint4) into 8 fp32 accumulators
__device__ __forceinline__ void acc8(float* acc, uint4 u) {
    float2 f;
    f = __half22float2(*(__half2*)&u.x); acc[0] += f.x; acc[1] += f.y;
    f = __half22float2(*(__half2*)&u.y); acc[2] += f.x; acc[3] += f.y;
    f = __half22float2(*(__half2*)&u.z); acc[4] += f.x; acc[5] += f.y;
    f = __half22float2(*(__half2*)&u.w); acc[6] += f.x; acc[7] += f.y;
}

// ---------------- init: zero counters + dtype probe (block 0) ----------------
__global__ void k_init(const int* __restrict__ ei32) {
    int i = blockIdx.x * 256 + threadIdx.x;
    if (i < N_NODES) { g_deg[i] = 0; g_cur[i] = 0; }
    if (i == 0) g_total = 0;
    if (blockIdx.x == 0) {
        __shared__ int anyNZ;
        if (threadIdx.x == 0) anyNZ = 0;
        __syncthreads();
        int nz = 0;
        #pragma unroll
        for (int j = 0; j < 8; j++) {
            int idx = 2 * (threadIdx.x + 256 * j) + 1;   // odd words
            if (ei32[idx] != 0) nz = 1;
        }
        if (nz) atomicOr(&anyNZ, 1);
        __syncthreads();
        if (threadIdx.x == 0) g_is64 = anyNZ ? 0 : 1;
    }
}

__device__ __forceinline__ int edge_at(const void* ei, long long idx) {
    if (g_is64) return (int)((const long long*)ei)[idx];
    return ((const int*)ei)[idx];
}

// ---------------- graph build ------------------------------------------------
__global__ void k_count(const void* __restrict__ ei) {
    int e = blockIdx.x * blockDim.x + threadIdx.x;
    if (e < N_EDGES) {
        int c = edge_at(ei, (long long)N_EDGES + e);
        if ((unsigned)c < N_NODES) atomicAdd(&g_deg[c], 1);
    }
}

// fused per-block scan + atomic block base + dinv
__global__ void k_offa() {
    __shared__ int sh[256];
    __shared__ int base;
    int t = threadIdx.x;
    int i = blockIdx.x * 256 + t;
    int d = (i < N_NODES) ? g_deg[i] : 0;
    sh[t] = d;
    __syncthreads();
    #pragma unroll
    for (int off = 1; off < 256; off <<= 1) {
        int u = (t >= off) ? sh[t - off] : 0;
        __syncthreads();
        sh[t] += u;
        __syncthreads();
    }
    if (t == 255) base = atomicAdd(&g_total, sh[255]);
    __syncthreads();
    if (i < N_NODES) {
        g_off[i] = base + sh[t] - d;
        g_dinv[i] = rsqrtf((float)(d + 1));
    }
}

__global__ void k_fill(const void* __restrict__ ei) {
    int e = blockIdx.x * blockDim.x + threadIdx.x;
    if (e < N_EDGES) {
        int r = edge_at(ei, e);
        int c = edge_at(ei, (long long)N_EDGES + e);
        if ((unsigned)r >= N_NODES || (unsigned)c >= N_NODES) return;
        int pos = g_off[c] + atomicAdd(&g_cur[c], 1);
        if ((unsigned)pos < N_EDGES) g_src[pos] = r;
    }
}

// ---------------- bf16 3-term mma.sync GEMM, cp.async pipelined --------------
// g_h16[m][n] = fp16( dinv[m] * sum_k X[m][k] W[k][n] )
// Raw X staged via cp.async (depth 2, register-free); fp32->bf16 hi/lo frag
// conversion is smem->smem; single frag buffer. 48 KB static smem total.
__global__ void __launch_bounds__(256, 2) k_mgemm(const float* __restrict__ Xext,
                                                  const float* __restrict__ W,
                                                  int srcSel) {
    __shared__ __align__(16) float    sRaw[2][32 * 128];  // 32 KB
    __shared__ uint32_t sHi[16 * 128];                     // 8 KB
    __shared__ uint32_t sLo[16 * 128];                     // 8 KB

    const float* X = srcSel ? g_buf1 : Xext;
    __half2*     H = g_h16;

    int tid = threadIdx.x, wid = tid >> 5, lane = tid & 31;
    int nbase = wid * 16;

    // ---- W fragments (hi+lo) in registers, once per CTA ----
    uint32_t Whi[8][2][2], Wlo[8][2][2];
    #pragma unroll
    for (int ks = 0; ks < 8; ks++) {
        #pragma unroll
        for (int nb = 0; nb < 2; nb++) {
            int col = nbase + nb * 8 + (lane >> 2);
            int k0  = ks * 16 + (lane & 3) * 2;
            float w00 = W[(k0 + 0) * 128 + col];
            float w01 = W[(k0 + 1) * 128 + col];
            float w10 = W[(k0 + 8) * 128 + col];
            float w11 = W[(k0 + 9) * 128 + col];
            float h00 = bf16_round(w00), h01 = bf16_round(w01);
            float h10 = bf16_round(w10), h11 = bf16_round(w11);
            Whi[ks][nb][0] = pack_bf16(h00, h01);
            Whi[ks][nb][1] = pack_bf16(h10, h11);
            Wlo[ks][nb][0] = pack_bf16(w00 - h00, w01 - h01);
            Wlo[ks][nb][1] = pack_bf16(w10 - h10, w11 - h11);
        }
    }

    int rowBase = blockIdx.x * 128;

    // frag store addresses (loop-invariant)
    int sAddr[4];
    #pragma unroll
    for (int i = 0; i < 4; i++) {
        int lin = tid + 256 * i;
        int rl = lin >> 5, kq = lin & 31;
        int mb = rl >> 4, rloc = rl & 15;
        int ks = kq >> 2;
        int j = ((rloc >> 3) & 1) + (((kq >> 1) & 1) << 1);
        int slot = (rloc & 7) * 4 + 2 * (kq & 1);
        int slot_sw = slot ^ (ks << 2);
        sAddr[i] = (mb * 8 + ks) * 128 + slot_sw * 4 + j;
    }

    // cp.async issue helper data: lin -> (rl, kq)
    uint32_t rawAddr0 = smem_u32(&sRaw[0][0]);
    uint32_t rawAddr1 = smem_u32(&sRaw[1][0]);

    // issue slab 0 and slab 1
    #pragma unroll
    for (int s = 0; s < 2; s++) {
        uint32_t base = s ? rawAddr1 : rawAddr0;
        #pragma unroll
        for (int i = 0; i < 4; i++) {
            int lin = tid + 256 * i;
            int rl = lin >> 5, kq = lin & 31;
            int gr = rowBase + s * 32 + rl;
            int ok = (gr < N_NODES);
            int grc = ok ? gr : 0;
            cp_async16(base + lin * 16,
                       X + (size_t)grc * 128 + kq * 4, ok ? 16 : 0);
        }
        CP_COMMIT();
    }

    #pragma unroll 1
    for (int slab = 0; slab < 4; slab++) {
        int buf = slab & 1;
        cp_wait<1>();          // this thread's copy of slab done
        __syncthreads();       // everyone's copy done; frag reads of slab-1 done

        // ---- convert raw fp32 -> bf16 hi/lo fragments (smem->smem) ----
        #pragma unroll
        for (int i = 0; i < 4; i++) {
            int lin = tid + 256 * i;
            float4 v = *(const float4*)&sRaw[buf][lin * 4];
            int base = sAddr[i];
            float hx = bf16_round(v.x), hy = bf16_round(v.y);
            float hz = bf16_round(v.z), hw = bf16_round(v.w);
            sHi[base]     = pack_bf16(hx, hy);
            sHi[base + 4] = pack_bf16(hz, hw);
            sLo[base]     = pack_bf16(v.x - hx, v.y - hy);
            sLo[base + 4] = pack_bf16(v.z - hz, v.w - hw);
        }
        __syncthreads();       // frags ready; raw[buf] free to refill

        // ---- issue cp.async for slab+2 into the buffer just drained ----
        if (slab < 2) {
            uint32_t base = buf ? rawAddr1 : rawAddr0;
            #pragma unroll
            for (int i = 0; i < 4; i++) {
                int lin = tid + 256 * i;
                int rl = lin >> 5, kq = lin & 31;
                int gr = rowBase + (slab + 2) * 32 + rl;
                int ok = (gr < N_NODES);
                int grc = ok ? gr : 0;
                cp_async16(base + lin * 16,
                           X + (size_t)grc * 128 + kq * 4, ok ? 16 : 0);
            }
        }
        CP_COMMIT();           // keep group count consistent every slab

        // ---- compute 2 m-blocks from frags (overlaps the async copy) ----
        #pragma unroll 1
        for (int mb = 0; mb < 2; mb++) {
            float a0[2][4], a1[2][4], a2[2][4];
            #pragma unroll
            for (int nb = 0; nb < 2; nb++)
                #pragma unroll
                for (int j = 0; j < 4; j++) { a0[nb][j] = 0.f; a1[nb][j] = 0.f; a2[nb][j] = 0.f; }

            #pragma unroll
            for (int ks = 0; ks < 8; ks++) {
                int idx = (mb * 8 + ks) * 128 + (lane ^ (ks << 2)) * 4;
                uint4 ah = *(const uint4*)&sHi[idx];
                uint4 al = *(const uint4*)&sLo[idx];
                #pragma unroll
                for (int nb = 0; nb < 2; nb++) {
                    mma_bf16(a0[nb], ah.x, ah.y, ah.z, ah.w,
                             Whi[ks][nb][0], Whi[ks][nb][1]);
                    mma_bf16(a1[nb], al.x, al.y, al.z, al.w,
                             Whi[ks][nb][0], Whi[ks][nb][1]);
                    mma_bf16(a2[nb], ah.x, ah.y, ah.z, ah.w,
                             Wlo[ks][nb][0], Wlo[ks][nb][1]);
                }
            }

            int r0 = rowBase + slab * 32 + mb * 16 + (lane >> 2);
            int r1 = r0 + 8;
            float d0 = (r0 < N_NODES) ? g_dinv[r0] : 0.f;
            float d1 = (r1 < N_NODES) ? g_dinv[r1] : 0.f;
            #pragma unroll
            for (int nb = 0; nb < 2; nb++) {
                int cc = nbase + nb * 8 + (lane & 3) * 2;
                float s0 = a0[nb][0] + a1[nb][0] + a2[nb][0];
                float s1 = a0[nb][1] + a1[nb][1] + a2[nb][1];
                float s2 = a0[nb][2] + a1[nb][2] + a2[nb][2];
                float s3 = a0[nb][3] + a1[nb][3] + a2[nb][3];
                if (r0 < N_NODES)
                    H[(size_t)r0 * 64 + (cc >> 1)] = __floats2half2_rn(s0 * d0, s1 * d0);
                if (r1 < N_NODES)
                    H[(size_t)r1 * 64 + (cc >> 1)] = __floats2half2_rn(s2 * d1, s3 * d1);
            }
        }
    }
}

// ---------------- aggregation: 2 edges per LDG.128, shfl combine -------------
// out[c] = dinv[c]*(xts16[c] + sum_in xts16[s]) + bias
__global__ void __launch_bounds__(256) k_agg(const float* __restrict__ bias,
                                             float* __restrict__ outExt,
                                             int useExtOut) {
    int gw = (blockIdx.x * blockDim.x + threadIdx.x) >> 5;
    int lane = threadIdx.x & 31;
    if (gw >= N_NODES) return;
    int c = gw;
    int sub = lane >> 4;
    int ln  = lane & 15;

    const uint4* hv4 = (const uint4*)g_h16;
    float*       out = useExtOut ? outExt : g_buf1;

    float acc[8];
    #pragma unroll
    for (int j = 0; j < 8; j++) acc[j] = 0.f;

    if (sub == 0) acc8(acc, hv4[(size_t)c * 16 + ln]);   // self term

    int e0 = g_off[c];
    int e1 = e0 + g_deg[c];
    int e = e0;

    for (; e + 8 <= e1; e += 8) {
        int s0 = __ldg(&g_src[e     + sub]);
        int s1 = __ldg(&g_src[e + 2 + sub]);
        int s2 = __ldg(&g_src[e + 4 + sub]);
        int s3 = __ldg(&g_src[e + 6 + sub]);
        uint4 u0 = hv4[(size_t)s0 * 16 + ln];
        uint4 u1 = hv4[(size_t)s1 * 16 + ln];
        uint4 u2 = hv4[(size_t)s2 * 16 + ln];
        uint4 u3 = hv4[(size_t)s3 * 16 + ln];
        acc8(acc, u0); acc8(acc, u1); acc8(acc, u2); acc8(acc, u3);
    }
    for (; e < e1; e += 2) {
        int idx = e + sub;
        if (idx < e1) {
            int s = __ldg(&g_src[idx]);
            acc8(acc, hv4[(size_t)s * 16 + ln]);
        }
    }

    float res[8];
    #pragma unroll
    for (int j = 0; j < 8; j++)
        res[j] = acc[j] + __shfl_xor_sync(0xFFFFFFFFu, acc[j], 16);

    float dc = g_dinv[c];
    int o0 = sub * 4;
    int fslot = ln * 2 + sub;
    float4 b = ((const float4*)bias)[fslot];
    float4 o = make_float4(res[o0 + 0] * dc + b.x, res[o0 + 1] * dc + b.y,
                           res[o0 + 2] * dc + b.z, res[o0 + 3] * dc + b.w);
    ((float4*)out)[(size_t)c * 32 + fslot] = o;
}

// ---------------- launch -----------------------------------------------------
extern "C" void kernel_launch(void* const* d_in, const int* in_sizes, int n_in,
                              void* d_out, int out_size) {
    const float* X  = (const float*)d_in[0];
    const void*  EI = d_in[1];
    const float* W1 = (const float*)d_in[2];
    const float* B1 = (const float*)d_in[3];
    const float* W2 = (const float*)d_in[4];
    const float* B2 = (const float*)d_in[5];
    float*       out = (float*)d_out;

    const int edgeBlocks = (N_EDGES + 255) / 256;
    const int aggBlocks  = (N_NODES * 32 + 255) / 256;

    k_init<<<NBLK, 256>>>((const int*)EI);            // 0
    k_count<<<edgeBlocks, 256>>>(EI);                 // 1
    k_offa<<<NBLK, 256>>>();                          // 2
    k_mgemm<<<N_TILES, 256>>>(X, W1, /*src=*/0);      // 3 <- profiled launch
    k_fill<<<edgeBlocks, 256>>>(EI);                  // 4
    k_agg<<<aggBlocks, 256>>>(B1, out, 0);            // 5: h -> buf1
    k_mgemm<<<N_TILES, 256>>>(nullptr, W2, /*src=*/1);// 6
    k_agg<<<aggBlocks, 256>>>(B2, out, 1);            // 7: -> d_out
}